// round 15
// baseline (speedup 1.0000x reference)
#include <cuda_runtime.h>
#include <cuda_bf16.h>
#include <math.h>
#include <stdint.h>

#define Bsz 1024
#define Kn  20
#define DN  172
#define DE  172
#define QD  272
#define KDd 444
#define M2  (Bsz*Kn)      // 20480
#define MT  (M2+Bsz)      // 21504 = 168*128
#define QPAD  320
#define KVPAD 448
#define HPAD  192
#define WSP   896   // packed 2 heads x 448
#define QKN   960
#define NNODE 100001

// ---------------- device scratch ----------------
__device__ __align__(128) float g_nsum[(size_t)NNODE*DN];
__device__ __align__(128) float g_qk[(size_t)MT*WSP];
__device__ __align__(128) __nv_bfloat16 g_ws_hi[(size_t)MT*WSP];
__device__ __align__(128) __nv_bfloat16 g_ws_lo[(size_t)MT*WSP];
__device__ __align__(128) float g_o[(size_t)MT*QD];
__device__ __align__(128) __nv_bfloat16 g_qin_hi[(size_t)MT*QPAD];
__device__ __align__(128) __nv_bfloat16 g_qin_lo[(size_t)MT*QPAD];
__device__ __align__(128) __nv_bfloat16 g_cat_hi[(size_t)MT*KVPAD];
__device__ __align__(128) __nv_bfloat16 g_cat_lo[(size_t)MT*KVPAD];
__device__ __align__(128) __nv_bfloat16 g_h_hi[(size_t)MT*HPAD];
__device__ __align__(128) __nv_bfloat16 g_h_lo[(size_t)MT*HPAD];
__device__ __align__(128) float g_conv[(size_t)MT*DN];
__device__ __align__(128) float g_qkbias[2*WSP];
__device__ __align__(128) __nv_bfloat16 g_wqkt[2][2][QKN*QPAD];
__device__ __align__(128) __nv_bfloat16 g_wvot[2][2][288*WSP];
__device__ __align__(128) __nv_bfloat16 g_w1t[2][2][HPAD*KVPAD];
__device__ __align__(128) __nv_bfloat16 g_w2t[2][2][HPAD*HPAD];

// ---------------- helpers ----------------
__device__ __forceinline__ uint32_t smem_u32(const void* p) {
    uint32_t a;
    asm("{ .reg .u64 t; cvta.to.shared.u64 t, %1; cvt.u32.u64 %0, t; }" : "=r"(a) : "l"(p));
    return a;
}
__device__ __forceinline__ void cpa16(uint32_t s, const void* g) {
    asm volatile("cp.async.cg.shared.global [%0], [%1], 16;" :: "r"(s), "l"(g));
}
#define CP_COMMIT() asm volatile("cp.async.commit_group;" ::: "memory")
#define CP_WAIT1()  asm volatile("cp.async.wait_group 1;" ::: "memory")
#define CP_WAIT0()  asm volatile("cp.async.wait_group 0;" ::: "memory")

__device__ __forceinline__ void ldsm4(uint32_t* r, uint32_t a) {
    asm volatile("ldmatrix.sync.aligned.m8n8.x4.shared.b16 {%0,%1,%2,%3}, [%4];"
        : "=r"(r[0]), "=r"(r[1]), "=r"(r[2]), "=r"(r[3]) : "r"(a));
}
__device__ __forceinline__ void mma16816(float* c, const uint32_t* a, const uint32_t* b) {
    asm volatile("mma.sync.aligned.m16n8k16.row.col.f32.bf16.bf16.f32 "
        "{%0,%1,%2,%3}, {%4,%5,%6,%7}, {%8,%9}, {%0,%1,%2,%3};"
        : "+f"(c[0]), "+f"(c[1]), "+f"(c[2]), "+f"(c[3])
        : "r"(a[0]), "r"(a[1]), "r"(a[2]), "r"(a[3]), "r"(b[0]), "r"(b[1]));
}
__device__ __forceinline__ void split_bf16(float v, __nv_bfloat16& hi, __nv_bfloat16& lo) {
    hi = __float2bfloat16(v);
    lo = __float2bfloat16(v - __bfloat162float(hi));
}
__device__ __forceinline__ float join_bf16(__nv_bfloat16 hi, __nv_bfloat16 lo) {
    return __bfloat162float(hi) + __bfloat162float(lo);
}

// ---------------- mma.sync GEMM v4: CTA 128x96, 4 warps 2(M)x2(N), warp 64x48 ----
// 128 threads/CTA -> 255-reg budget; 2 CTAs/SM; 3-stage single-sync pipeline.
#define ASTR 80
#define A_BYTES 10240
#define W_BYTES 7680
#define STAGE_B 35840
#define NSTAGE 3

__global__ void __launch_bounds__(128, 2) mma_gemm_kernel(
    const __nv_bfloat16* __restrict__ Ahi, const __nv_bfloat16* __restrict__ Alo,
    const __nv_bfloat16* __restrict__ Whi, const __nv_bfloat16* __restrict__ Wlo,
    const float* __restrict__ bias, int relu,
    float* __restrict__ outF, __nv_bfloat16* __restrict__ outHi, __nv_bfloat16* __restrict__ outLo,
    int Kpad, int Klog, int Nlog, int padKout)
{
    extern __shared__ __align__(128) char smem[];
    const uint32_t sb = smem_u32(smem);
    const int tid = threadIdx.x, lane = tid & 31, wid = tid >> 5;
    const int wm = wid & 1, wn = wid >> 1;   // 2(M) x 2(N) warps
    const int m0 = blockIdx.y * 128;
    const int bn0w = blockIdx.x * 96;
    const int nch = (Klog + 31) >> 5;
    const int kstot = (Klog + 15) >> 4;

    float acc[4][6][4];
#pragma unroll
    for (int i = 0; i < 4; i++)
#pragma unroll
        for (int j = 0; j < 6; j++)
#pragma unroll
            for (int e = 0; e < 4; e++) acc[i][j][e] = 0.f;

    auto issue = [&](int c) {
        uint32_t st = sb + (uint32_t)(c % NSTAGE) * STAGE_B;
        int gk = c * 32;
        // A: 2 bufs x 128 rows x 4 chunks = 1024 chunks over 128 threads
#pragma unroll
        for (int i = 0; i < 8; i++) {
            int qq = tid + i * 128;
            int buf = qq >> 9, rem = qq & 511, row = rem >> 2, ch = rem & 3;
            const __nv_bfloat16* g = (buf ? Alo : Ahi) + (size_t)(m0 + row) * Kpad + gk + ch * 8;
            cpa16(st + (uint32_t)buf * A_BYTES + row * ASTR + ch * 16, g);
        }
        // W: 2 bufs x 96 rows x 4 chunks = 768 chunks
#pragma unroll
        for (int i = 0; i < 6; i++) {
            int qq = tid + i * 128;
            int buf = qq / 384, rem = qq - buf * 384, row = rem >> 2, ch = rem & 3;
            const __nv_bfloat16* g = (buf ? Wlo : Whi) + (size_t)(bn0w + row) * Kpad + gk + ch * 8;
            cpa16(st + 2 * A_BYTES + (uint32_t)buf * W_BYTES + row * ASTR + ch * 16, g);
        }
        CP_COMMIT();
    };

    issue(0);
    if (nch > 1) issue(1);

    const int arow = wm * 64 + (lane & 15);
    const uint32_t acolb = ((lane >> 4) * 8) * 2;
    const int brow = wn * 48 + (lane & 7) + ((lane >> 4) & 1) * 8;
    const uint32_t bcolb = (((lane >> 3) & 1) * 8) * 2;

    for (int c = 0; c < nch; c++) {
        uint32_t st = sb + (uint32_t)(c % NSTAGE) * STAGE_B;
        if (c + 1 < nch) { CP_WAIT1(); } else { CP_WAIT0(); }
        __syncthreads();
        if (c + 2 < nch) issue(c + 2);
        const uint32_t aHiB = st + arow * ASTR;
        const uint32_t aLoB = aHiB + A_BYTES;
        const uint32_t wHiB = st + 2 * A_BYTES + brow * ASTR;
        const uint32_t wLoB = wHiB + W_BYTES;
#pragma unroll
        for (int ks = 0; ks < 2; ks++) {
            if (c * 2 + ks >= kstot) break;
            const uint32_t ka = acolb + ks * 32;
            const uint32_t kb = bcolb + ks * 32;
            uint32_t ah[16], al[16], bh[12], bl[12];
#pragma unroll
            for (int mi = 0; mi < 4; mi++) {
                ldsm4(ah + 4 * mi, aHiB + mi * 16 * ASTR + ka);
                ldsm4(al + 4 * mi, aLoB + mi * 16 * ASTR + ka);
            }
#pragma unroll
            for (int p = 0; p < 3; p++) {
                ldsm4(bh + 4 * p, wHiB + p * 16 * ASTR + kb);
                ldsm4(bl + 4 * p, wLoB + p * 16 * ASTR + kb);
            }
#pragma unroll
            for (int mi = 0; mi < 4; mi++)
#pragma unroll
                for (int ni = 0; ni < 6; ni++) {
                    mma16816(acc[mi][ni], ah + 4 * mi, bh + 2 * ni);
                    mma16816(acc[mi][ni], al + 4 * mi, bh + 2 * ni);
                    mma16816(acc[mi][ni], ah + 4 * mi, bl + 2 * ni);
                }
        }
    }

    const __nv_bfloat16 bz = __float2bfloat16(0.f);
#pragma unroll
    for (int mi = 0; mi < 4; mi++)
#pragma unroll
        for (int ni = 0; ni < 6; ni++) {
            int r0 = m0 + wm * 64 + mi * 16 + (lane >> 2);
            int col = bn0w + wn * 48 + ni * 8 + ((lane & 3) << 1);
#pragma unroll
            for (int e = 0; e < 4; e++) {
                int rr = r0 + (e >> 1) * 8;
                int cc = col + (e & 1);
                if (cc < Nlog) {
                    float vv = acc[mi][ni][e];
                    if (bias) vv += bias[cc];
                    if (relu) vv = fmaxf(vv, 0.f);
                    if (outF) outF[(size_t)rr * Nlog + cc] = vv;
                    if (outHi) {
                        __nv_bfloat16 hi, lo; split_bf16(vv, hi, lo);
                        outHi[(size_t)rr * padKout + cc] = hi;
                        outLo[(size_t)rr * padKout + cc] = lo;
                    }
                } else if (outHi && cc < padKout) {
                    outHi[(size_t)rr * padKout + cc] = bz;
                    outLo[(size_t)rr * padKout + cc] = bz;
                }
            }
        }
}

// ---------------- presum node tables ----------------
__global__ void __launch_bounds__(256) presum_kernel(const float* __restrict__ a,
                                                     const float* __restrict__ b,
                                                     float* __restrict__ o, size_t n4)
{
    size_t i = (size_t)blockIdx.x * blockDim.x + threadIdx.x;
    size_t st = (size_t)gridDim.x * blockDim.x;
    const float4* a4 = (const float4*)a;
    const float4* b4 = (const float4*)b;
    float4* o4 = (float4*)o;
    for (; i < n4; i += st) {
        float4 x = a4[i], y = b4[i];
        o4[i] = make_float4(x.x + y.x, x.y + y.y, x.z + y.z, x.w + y.w);
    }
}

// ---------------- weight transpose+split for m1/m2 ----------------
struct WJob { const float* src; __nv_bfloat16* hi; __nv_bfloat16* lo; int Kd, N, Kpad; };
struct WJobs { WJob j[4]; };

__global__ void __launch_bounds__(1024) wconv_all(WJobs jobs) {
    WJob jb = jobs.j[blockIdx.z];
    int k0 = blockIdx.x * 32, n0 = blockIdx.y * 32;
    if (k0 >= jb.Kpad) return;
    __shared__ float t[32][33];
    int tx = threadIdx.x, ty = threadIdx.y;
    float v = 0.f;
    if (k0 + ty < jb.Kd && n0 + tx < jb.N)
        v = jb.src[(size_t)(k0 + ty) * jb.N + n0 + tx];
    t[ty][tx] = v;
    __syncthreads();
    int n = n0 + ty, k = k0 + tx;
    if (n < HPAD && k < jb.Kpad) {
        __nv_bfloat16 h, l; split_bf16(t[tx][ty], h, l);
        jb.hi[(size_t)n * jb.Kpad + k] = h;
        jb.lo[(size_t)n * jb.Kpad + k] = l;
    }
}

// ---------------- merged folded-weight precompute ----------------
// z in 0..1: Wqk layer z;  z in 2..3: Wvo layer z-2. Layer stride = 2*plane.
__global__ void __launch_bounds__(256) wfold_build(
    const float* __restrict__ Wq, const float* __restrict__ Wk,
    const float* __restrict__ Wv, const float* __restrict__ Wo,
    __nv_bfloat16* __restrict__ qkhi, __nv_bfloat16* __restrict__ qklo,
    __nv_bfloat16* __restrict__ vohi, __nv_bfloat16* __restrict__ volo)
{
    extern __shared__ float ps[];
    float* As = ps;
    float* Bs = ps + 64 * 137;
    int z = blockIdx.z;
    int tx = threadIdx.x & 15, ty = threadIdx.x >> 4;

    if (z < 2) {
        if (blockIdx.x >= QPAD / 64) return;
        int l = z;
        const float* wq = Wq + (size_t)l * QD * QD;
        const float* wk = Wk + (size_t)l * KDd * QD;
        __nv_bfloat16* hi = qkhi + (size_t)l * (2 * QKN * QPAD);
        __nv_bfloat16* lo = qklo + (size_t)l * (2 * QKN * QPAD);
        int kb = blockIdx.x * 64, nb = blockIdx.y * 64;
        int h = nb / 448;
        for (int e = threadIdx.x; e < 64 * 136; e += 256) {
            int nl = e / 136, d = e - nl * 136;
            int dp = nb + nl - h * 448;
            float v = 0.f;
            if (h < 2 && dp < 444) v = wk[(size_t)dp * 272 + h * 136 + d];
            As[nl * 137 + d] = v;
        }
        for (int e = threadIdx.x; e < 64 * 136; e += 256) {
            int kl = e / 136, d = e - kl * 136;
            int k = kb + kl;
            float v = 0.f;
            if (h < 2 && k < 272) v = wq[(size_t)k * 272 + h * 136 + d];
            Bs[kl * 137 + d] = v;
        }
        __syncthreads();
        float acc[4][4] = {};
        for (int d = 0; d < 136; d++) {
            float a[4], b[4];
#pragma unroll
            for (int i = 0; i < 4; i++) a[i] = As[(ty * 4 + i) * 137 + d];
#pragma unroll
            for (int j = 0; j < 4; j++) b[j] = Bs[(tx * 4 + j) * 137 + d];
#pragma unroll
            for (int i = 0; i < 4; i++)
#pragma unroll
                for (int j = 0; j < 4; j++) acc[i][j] += a[i] * b[j];
        }
#pragma unroll
        for (int i = 0; i < 4; i++)
#pragma unroll
            for (int j = 0; j < 4; j++) {
                int n = nb + ty * 4 + i, k = kb + tx * 4 + j;
                __nv_bfloat16 hh, ll; split_bf16(acc[i][j], hh, ll);
                hi[(size_t)n * QPAD + k] = hh;
                lo[(size_t)n * QPAD + k] = ll;
            }
    } else {
        if (blockIdx.y >= 5) return;
        int l = z - 2;
        const float* wv = Wv + (size_t)l * KDd * QD;
        const float* wo = Wo + (size_t)l * QD * QD;
        __nv_bfloat16* hi = vohi + (size_t)l * (2 * 288 * WSP);
        __nv_bfloat16* lo = volo + (size_t)l * (2 * 288 * WSP);
        int kkb = blockIdx.x * 64, nb = blockIdx.y * 64;
        int h = kkb / 448;
        for (int e = threadIdx.x; e < 64 * 136; e += 256) {
            int kl = e / 136, d = e - kl * 136;
            int dp = kkb + kl - h * 448;
            float v = 0.f;
            if (dp < 444) v = wv[(size_t)dp * 272 + h * 136 + d];
            As[kl * 137 + d] = v;
        }
        for (int e = threadIdx.x; e < 64 * 136; e += 256) {
            int d = e >> 6, nl = e & 63;
            int n = nb + nl;
            float v = 0.f;
            if (n < 272) v = wo[(size_t)(h * 136 + d) * 272 + n];
            Bs[nl * 137 + d] = v;
        }
        __syncthreads();
        float acc[4][4] = {};
        for (int d = 0; d < 136; d++) {
            float a[4], b[4];
#pragma unroll
            for (int i = 0; i < 4; i++) a[i] = As[(ty * 4 + i) * 137 + d];
#pragma unroll
            for (int j = 0; j < 4; j++) b[j] = Bs[(tx * 4 + j) * 137 + d];
#pragma unroll
            for (int i = 0; i < 4; i++)
#pragma unroll
                for (int j = 0; j < 4; j++) acc[i][j] += a[i] * b[j];
        }
#pragma unroll
        for (int i = 0; i < 4; i++)
#pragma unroll
            for (int j = 0; j < 4; j++) {
                int kk = kkb + ty * 4 + i, n = nb + tx * 4 + j;
                if (n < 288) {
                    __nv_bfloat16 hh, ll; split_bf16(acc[i][j], hh, ll);
                    hi[(size_t)n * WSP + kk] = hh;
                    lo[(size_t)n * WSP + kk] = ll;
                }
            }
    }
}

// qk_bias[l][n] = sum_{j<DT} cos(time_b[j]) * Wqkt[l][n][DN+j]
__global__ void __launch_bounds__(128) qkbias_build(const __nv_bfloat16* __restrict__ hi,
                                                    const __nv_bfloat16* __restrict__ lo,
                                                    const float* __restrict__ time_b,
                                                    float* __restrict__ bias, size_t lstride)
{
    int n = blockIdx.x, l = blockIdx.y;
    const __nv_bfloat16* ph = hi + (size_t)l * lstride + (size_t)n * QPAD + DN;
    const __nv_bfloat16* pl = lo + (size_t)l * lstride + (size_t)n * QPAD + DN;
    __shared__ float red[4];
    int tid = threadIdx.x;
    float s = 0.f;
    for (int j = tid; j < 100; j += 128)
        s += cosf(time_b[j]) * (__bfloat162float(ph[j]) + __bfloat162float(pl[j]));
#pragma unroll
    for (int o = 16; o; o >>= 1) s += __shfl_xor_sync(0xffffffffu, s, o);
    if ((tid & 31) == 0) red[tid >> 5] = s;
    __syncthreads();
    if (tid == 0)
        bias[(size_t)l * WSP + n] = red[0] + red[1] + red[2] + red[3];
}

// ---------------- feature builds ----------------
__global__ void build_nf_qin(const int* __restrict__ idsA, const int* __restrict__ idsB, int nA,
                             const float* __restrict__ memories, const float* __restrict__ node_raw,
                             __nv_bfloat16* __restrict__ qhi, __nv_bfloat16* __restrict__ qlo)
{
    int m = blockIdx.x;
    int id = (m < nA) ? idsA[m] : idsB[m - nA];
    for (int j = threadIdx.x; j < QPAD; j += blockDim.x) {
        float v = (j < DN) ? memories[(size_t)id * DN + j] + node_raw[(size_t)id * DN + j] : 0.f;
        __nv_bfloat16 h, l; split_bf16(v, h, l);
        qhi[(size_t)m * QPAD + j] = h;
        qlo[(size_t)m * QPAD + j] = l;
    }
}

__global__ void build_qin_conv(const float* __restrict__ conv,
                               __nv_bfloat16* __restrict__ qhi, __nv_bfloat16* __restrict__ qlo)
{
    int m = blockIdx.x;
    for (int j = threadIdx.x; j < QPAD; j += blockDim.x) {
        float v = (j < DN) ? conv[(size_t)m * DN + j] : 0.f;
        __nv_bfloat16 h, l; split_bf16(v, h, l);
        qhi[(size_t)m * QPAD + j] = h;
        qlo[(size_t)m * QPAD + j] = l;
    }
}

// ---------------- fused kv-build + attention + weighted-sum ----------------
__global__ void __launch_bounds__(256) attn_fused(
    const float* __restrict__ qk,
    const float* __restrict__ feat,          // null -> gather nsum
    const int* __restrict__ idsA, const int* __restrict__ eidsA,
    const float* __restrict__ tA, const float* __restrict__ ntA, int nA,
    const int* __restrict__ idsB, const int* __restrict__ eidsB,
    const float* __restrict__ tB, const float* __restrict__ ntB,
    const float* __restrict__ nsum, const float* __restrict__ edge_raw,
    const float* __restrict__ time_w, const float* __restrict__ time_b,
    __nv_bfloat16* __restrict__ wshi, __nv_bfloat16* __restrict__ wslo)
{
    const float SCALE = 0.08574929257125442f;   // 136^-0.5
    __shared__ __align__(16) float kvs[Kn][KVPAD];
    __shared__ __align__(16) float qks[WSP];
    __shared__ float att[2 * Kn];
    __shared__ int   sids[Kn];

    int m = blockIdx.x;
    int tid = threadIdx.x, wid = tid >> 5, lane = tid & 31;
    const uint32_t kvs_b = smem_u32(kvs);

    const int* nbr_ids; const int* nbr_eids; const float* nbr_t; float tm;
    if (m < nA) {
        nbr_ids = idsA + (size_t)m * Kn;
        nbr_eids = eidsA + (size_t)m * Kn;
        nbr_t = ntA + (size_t)m * Kn;
        tm = tA[m];
    } else {
        int mm = m - nA;
        nbr_ids = idsB + (size_t)mm * Kn;
        nbr_eids = eidsB + (size_t)mm * Kn;
        nbr_t = ntB + (size_t)mm * Kn;
        tm = tB[mm];
    }

    if (tid < Kn) sids[tid] = nbr_ids[tid];
    if (tid < 224)
        cpa16(smem_u32(qks) + tid * 16, (const float4*)(qk + (size_t)m * WSP) + tid);

    for (int p = wid; p < Kn; p += 8) {
        int nid = nbr_ids[p];
        int eid = nbr_eids[p];
        const float4* nsrc = feat ? (const float4*)(feat + ((size_t)m * Kn + p) * DN)
                                  : (const float4*)(nsum + (size_t)nid * DN);
        const float4* esrc = (const float4*)(edge_raw + (size_t)eid * DE);
        uint32_t dst = kvs_b + (uint32_t)p * (KVPAD * 4);
#pragma unroll
        for (int it = 0; it < 3; it++) {
            int ch = lane + it * 32;
            if (ch < 86) {
                if (ch < 43) cpa16(dst + ch * 16, nsrc + ch);
                else         cpa16(dst + 688 + (ch - 43) * 16, esrc + (ch - 43));
            }
        }
        float dt = __fadd_rn(tm, -nbr_t[p]);
#pragma unroll
        for (int it = 0; it < 4; it++) {
            int j = lane + it * 32;
            if (j < 100)
                kvs[p][344 + j] = cosf(__fadd_rn(__fmul_rn(dt, time_w[j]), time_b[j]));
        }
        if (lane < 4) kvs[p][444 + lane] = 0.f;
    }
    CP_COMMIT();
    CP_WAIT0();
    __syncthreads();

    for (int p = wid; p < 2 * Kn; p += 8) {
        int h = p / Kn, kk = p % Kn;
        const float* qrow = qks + h * 448;
        float s = 0.f;
        for (int d = lane; d < KDd; d += 32) s += qrow[d] * kvs[kk][d];
#pragma unroll
        for (int o = 16; o; o >>= 1) s += __shfl_xor_sync(0xffffffffu, s, o);
        if (lane == 0)
            att[p] = (sids[kk] == 0) ? -1e10f : s * SCALE;
    }
    __syncthreads();

    if (tid < 2) {
        int h = tid;
        float mx = -INFINITY;
        for (int kk = 0; kk < Kn; kk++) mx = fmaxf(mx, att[h * Kn + kk]);
        float sum = 0.f;
        for (int kk = 0; kk < Kn; kk++) { float e = expf(att[h*Kn+kk] - mx); att[h*Kn+kk] = e; sum += e; }
        float inv = 1.f / sum;
        for (int kk = 0; kk < Kn; kk++) att[h * Kn + kk] *= inv;
    }
    __syncthreads();

    for (int j = tid; j < WSP; j += 256) {
        int h = j / 448, jj = j - h * 448;
        float acc = 0.f;
#pragma unroll
        for (int kk = 0; kk < Kn; kk++) acc += att[h * Kn + kk] * kvs[kk][jj];
        __nv_bfloat16 hi, lo; split_bf16(acc, hi, lo);
        wshi[(size_t)m * WSP + j] = hi;
        wslo[(size_t)m * WSP + j] = lo;
    }
}

// ---------------- residual + bias + LayerNorm + cat (hi/lo residual reconstruction) ---
__global__ void lncat_kernel(const float* __restrict__ o, const float* __restrict__ bo,
                             const __nv_bfloat16* __restrict__ resHi, const __nv_bfloat16* __restrict__ resLo,
                             const __nv_bfloat16* __restrict__ nfHi, const __nv_bfloat16* __restrict__ nfLo,
                             const float* __restrict__ time_b,
                             const float* __restrict__ gam, const float* __restrict__ bet,
                             __nv_bfloat16* __restrict__ chi, __nv_bfloat16* __restrict__ clo)
{
    int m = blockIdx.x;
    int tid = threadIdx.x;
    __shared__ float buf[QD];
    __shared__ float red[32];
    for (int j = tid; j < QD; j += 256) {
        float res = (j < DN)
            ? join_bf16(resHi[(size_t)m * QPAD + j], resLo[(size_t)m * QPAD + j])
            : cosf(time_b[j - DN]);
        buf[j] = o[(size_t)m * QD + j] + bo[j] + res;
    }
    __syncthreads();
    float s = 0.f;
    for (int j = tid; j < QD; j += 256) s += buf[j];
#pragma unroll
    for (int off = 16; off; off >>= 1) s += __shfl_xor_sync(0xffffffffu, s, off);
    if ((tid & 31) == 0) red[tid >> 5] = s;
    __syncthreads();
    if (tid < 32) {
        float t = (tid < 8) ? red[tid] : 0.f;
#pragma unroll
        for (int off = 4; off; off >>= 1) t += __shfl_xor_sync(0xffffffffu, t, off);
        if (tid == 0) red[0] = t;
    }
    __syncthreads();
    float mu = red[0] / (float)QD;
    __syncthreads();
    float s2 = 0.f;
    for (int j = tid; j < QD; j += 256) { float d = buf[j] - mu; s2 += d * d; }
#pragma unroll
    for (int off = 16; off; off >>= 1) s2 += __shfl_xor_sync(0xffffffffu, s2, off);
    if ((tid & 31) == 0) red[tid >> 5] = s2;
    __syncthreads();
    if (tid < 32) {
        float t = (tid < 8) ? red[tid] : 0.f;
#pragma unroll
        for (int off = 4; off; off >>= 1) t += __shfl_xor_sync(0xffffffffu, t, off);
        if (tid == 0) red[0] = t;
    }
    __syncthreads();
    float var = red[0] / (float)QD;
    float rinv = 1.0f / sqrtf(var + 1e-5f);
    for (int j = tid; j < KVPAD; j += 256) {
        float vv;
        if (j < QD)
            vv = (buf[j] - mu) * rinv * gam[j] + bet[j];
        else if (j < KDd)
            vv = join_bf16(nfHi[(size_t)m * QPAD + (j - QD)], nfLo[(size_t)m * QPAD + (j - QD)]);
        else
            vv = 0.f;
        __nv_bfloat16 hi, lo; split_bf16(vv, hi, lo);
        chi[(size_t)m * KVPAD + j] = hi;
        clo[(size_t)m * KVPAD + j] = lo;
    }
}

// ---------------- host ----------------
extern "C" void kernel_launch(void* const* d_in, const int* in_sizes, int n_in,
                              void* d_out, int out_size)
{
    (void)in_sizes; (void)n_in; (void)out_size;
    const float* node_raw = (const float*)d_in[0];
    const float* edge_raw = (const float*)d_in[1];
    const float* memories = (const float*)d_in[2];
    const float* t_node   = (const float*)d_in[3];
    const float* t_n1     = (const float*)d_in[4];
    const float* t_n2     = (const float*)d_in[5];
    const float* time_w   = (const float*)d_in[6];
    const float* time_b   = (const float*)d_in[7];
    const float* Wq       = (const float*)d_in[8];
    const float* Wk       = (const float*)d_in[9];
    const float* Wv       = (const float*)d_in[10];
    const float* Wo       = (const float*)d_in[11];
    const float* bo       = (const float*)d_in[12];
    const float* ln_g     = (const float*)d_in[13];
    const float* ln_b     = (const float*)d_in[14];
    const float* m_w1     = (const float*)d_in[15];
    const float* m_b1     = (const float*)d_in[16];
    const float* m_w2     = (const float*)d_in[17];
    const float* m_b2     = (const float*)d_in[18];
    const int* node_ids   = (const int*)d_in[19];
    const int* n1_ids     = (const int*)d_in[20];
    const int* n1_eids    = (const int*)d_in[21];
    const int* n2_ids     = (const int*)d_in[22];
    const int* n2_eids    = (const int*)d_in[23];
    float* out = (float*)d_out;

    float *nsum, *qkbuf, *obuf, *conv, *qkbias;
    __nv_bfloat16 *qin_hi, *qin_lo, *ws_hi, *ws_lo, *cat_hi, *cat_lo, *h_hi, *h_lo;
    __nv_bfloat16 *wqkt, *wvot, *w1t, *w2t;
    cudaGetSymbolAddress((void**)&nsum, g_nsum);
    cudaGetSymbolAddress((void**)&qkbuf, g_qk);
    cudaGetSymbolAddress((void**)&obuf, g_o);
    cudaGetSymbolAddress((void**)&conv, g_conv);
    cudaGetSymbolAddress((void**)&qkbias, g_qkbias);
    cudaGetSymbolAddress((void**)&qin_hi, g_qin_hi);
    cudaGetSymbolAddress((void**)&qin_lo, g_qin_lo);
    cudaGetSymbolAddress((void**)&ws_hi, g_ws_hi);
    cudaGetSymbolAddress((void**)&ws_lo, g_ws_lo);
    cudaGetSymbolAddress((void**)&cat_hi, g_cat_hi);
    cudaGetSymbolAddress((void**)&cat_lo, g_cat_lo);
    cudaGetSymbolAddress((void**)&h_hi, g_h_hi);
    cudaGetSymbolAddress((void**)&h_lo, g_h_lo);
    cudaGetSymbolAddress((void**)&wqkt, g_wqkt);
    cudaGetSymbolAddress((void**)&wvot, g_wvot);
    cudaGetSymbolAddress((void**)&w1t, g_w1t);
    cudaGetSymbolAddress((void**)&w2t, g_w2t);

    cudaFuncSetAttribute(mma_gemm_kernel, cudaFuncAttributeMaxDynamicSharedMemorySize, NSTAGE * STAGE_B);
    cudaFuncSetAttribute(wfold_build, cudaFuncAttributeMaxDynamicSharedMemorySize, 2 * 64 * 137 * 4);

    auto wpq = [&](int l, int hl) { return wqkt + ((size_t)(l * 2 + hl)) * (QKN * QPAD); };
    auto wpv = [&](int l, int hl) { return wvot + ((size_t)(l * 2 + hl)) * (288 * WSP); };
    auto wp1 = [&](int l, int hl) { return w1t + ((size_t)(l * 2 + hl)) * (HPAD * KVPAD); };
    auto wp2 = [&](int l, int hl) { return w2t + ((size_t)(l * 2 + hl)) * (HPAD * HPAD); };

    auto rungemm = [&](const __nv_bfloat16* aH, const __nv_bfloat16* aL,
                       const __nv_bfloat16* wH, const __nv_bfloat16* wL,
                       const float* bias, int relu, float* oF,
                       __nv_bfloat16* oH, __nv_bfloat16* oL,
                       int M, int Kpad, int Klog, int Nlog, int padKout) {
        dim3 grid((Nlog + 95) / 96, M / 128);
        mma_gemm_kernel<<<grid, 128, NSTAGE * STAGE_B>>>(aH, aL, wH, wL, bias, relu,
                                                         oF, oH, oL, Kpad, Klog, Nlog, padKout);
    };

    // 1: wfold  2: qkbias  3: build_nf  4: qk GEMM (profiled)
    wfold_build<<<dim3(WSP/64, QKN/64, 4), 256, 2*64*137*4>>>(
        Wq, Wk, Wv, Wo, wpq(0,0), wpq(0,1), wpv(0,0), wpv(0,1));
    qkbias_build<<<dim3(WSP, 2), 128>>>(wpq(0,0), wpq(0,1), time_b, qkbias,
                                        (size_t)2 * QKN * QPAD);
    build_nf_qin<<<MT, 256>>>(n1_ids, node_ids, M2, memories, node_raw, qin_hi, qin_lo);
    rungemm(qin_hi, qin_lo, wpq(0,0), wpq(0,1), qkbias, 0,
            qkbuf, nullptr, nullptr, MT, QPAD, DN, WSP, 0);
    presum_kernel<<<8192, 256>>>(memories, node_raw, nsum, (size_t)NNODE * DN / 4);
    WJobs jobs;
    for (int l = 0; l < 2; l++) {
        jobs.j[l*2+0] = { m_w1 + (size_t)l*KDd*DN, wp1(l,0), wp1(l,1), KDd, DN, KVPAD };
        jobs.j[l*2+1] = { m_w2 + (size_t)l*DN*DN,  wp2(l,0), wp2(l,1), DN,  DN, HPAD  };
    }
    wconv_all<<<dim3(KVPAD/32, HPAD/32, 4), dim3(32, 32)>>>(jobs);

    // ---- phase A+B tail ----
    attn_fused<<<MT, 256>>>(qkbuf, nullptr, n2_ids, n2_eids, t_n1, t_n2, M2,
                            n1_ids, n1_eids, t_node, t_n1,
                            nsum, edge_raw, time_w, time_b, ws_hi, ws_lo);
    rungemm(ws_hi, ws_lo, wpv(0,0), wpv(0,1), nullptr, 0,
            obuf, nullptr, nullptr, MT, WSP, WSP, QD, 0);
    lncat_kernel<<<MT, 256>>>(obuf, bo, qin_hi, qin_lo, qin_hi, qin_lo, time_b,
                              ln_g, ln_b, cat_hi, cat_lo);
    rungemm(cat_hi, cat_lo, wp1(0,0), wp1(0,1), m_b1, 1,
            nullptr, h_hi, h_lo, MT, KVPAD, KVPAD, DN, HPAD);
    rungemm(h_hi, h_lo, wp2(0,0), wp2(0,1), m_b2, 0,
            conv, nullptr, nullptr, MT, HPAD, DN, DN, 0);

    // ---- phase C: layer 1 over center nodes ----
    build_qin_conv<<<Bsz, 256>>>(conv + (size_t)M2 * DN, qin_hi, qin_lo);
    rungemm(qin_hi, qin_lo, wpq(1,0), wpq(1,1), qkbias + WSP, 0,
            qkbuf, nullptr, nullptr, Bsz, QPAD, DN, WSP, 0);
    attn_fused<<<Bsz, 256>>>(qkbuf, conv, n1_ids, n1_eids, t_node, t_n1, Bsz,
                             n1_ids, n1_eids, t_node, t_n1,
                             nsum, edge_raw, time_w, time_b, ws_hi, ws_lo);
    rungemm(ws_hi, ws_lo, wpv(1,0), wpv(1,1), nullptr, 0,
            obuf, nullptr, nullptr, Bsz, WSP, WSP, QD, 0);
    lncat_kernel<<<Bsz, 256>>>(obuf, bo + QD, qin_hi, qin_lo,
                               qin_hi + (size_t)M2 * QPAD, qin_lo + (size_t)M2 * QPAD,
                               time_b, ln_g + QD, ln_b + QD, cat_hi, cat_lo);
    rungemm(cat_hi, cat_lo, wp1(1,0), wp1(1,1), m_b1 + DN, 1,
            nullptr, h_hi, h_lo, Bsz, KVPAD, KVPAD, DN, HPAD);
    rungemm(h_hi, h_lo, wp2(1,0), wp2(1,1), m_b2 + DN, 0,
            out, nullptr, nullptr, Bsz, HPAD, DN, DN, 0);
}

// round 16
// speedup vs baseline: 1.0810x; 1.0810x over previous
#include <cuda_runtime.h>
#include <cuda_bf16.h>
#include <math.h>
#include <stdint.h>

#define Bsz 1024
#define Kn  20
#define DN  172
#define DE  172
#define QD  272
#define KDd 444
#define M2  (Bsz*Kn)      // 20480
#define MT  (M2+Bsz)      // 21504 = 168*128
#define QPAD  320
#define KVPAD 448
#define HPAD  192
#define WSP   896   // packed 2 heads x 448
#define QKN   960
#define NNODE 100001

// ---------------- device scratch ----------------
__device__ __align__(128) float g_nsum[(size_t)NNODE*DN];
__device__ __align__(128) float g_qk[(size_t)MT*WSP];
__device__ __align__(128) __nv_bfloat16 g_ws_hi[(size_t)MT*WSP];
__device__ __align__(128) __nv_bfloat16 g_ws_lo[(size_t)MT*WSP];
__device__ __align__(128) float g_o[(size_t)MT*QD];
__device__ __align__(128) __nv_bfloat16 g_qin_hi[(size_t)MT*QPAD];
__device__ __align__(128) __nv_bfloat16 g_qin_lo[(size_t)MT*QPAD];
__device__ __align__(128) __nv_bfloat16 g_cat_hi[(size_t)MT*KVPAD];
__device__ __align__(128) __nv_bfloat16 g_cat_lo[(size_t)MT*KVPAD];
__device__ __align__(128) __nv_bfloat16 g_h_hi[(size_t)MT*HPAD];
__device__ __align__(128) __nv_bfloat16 g_h_lo[(size_t)MT*HPAD];
__device__ __align__(128) float g_conv[(size_t)MT*DN];
__device__ __align__(128) float g_qkbias[2*WSP];
__device__ __align__(128) __nv_bfloat16 g_wqkt[2][2][QKN*QPAD];
__device__ __align__(128) __nv_bfloat16 g_wvot[2][2][288*WSP];
__device__ __align__(128) __nv_bfloat16 g_w1t[2][2][HPAD*KVPAD];
__device__ __align__(128) __nv_bfloat16 g_w2t[2][2][HPAD*HPAD];

// ---------------- helpers ----------------
__device__ __forceinline__ uint32_t smem_u32(const void* p) {
    uint32_t a;
    asm("{ .reg .u64 t; cvta.to.shared.u64 t, %1; cvt.u32.u64 %0, t; }" : "=r"(a) : "l"(p));
    return a;
}
__device__ __forceinline__ void cpa16(uint32_t s, const void* g) {
    asm volatile("cp.async.cg.shared.global [%0], [%1], 16;" :: "r"(s), "l"(g));
}
#define CP_COMMIT() asm volatile("cp.async.commit_group;" ::: "memory")
#define CP_WAIT1()  asm volatile("cp.async.wait_group 1;" ::: "memory")
#define CP_WAIT0()  asm volatile("cp.async.wait_group 0;" ::: "memory")

__device__ __forceinline__ void ldsm4(uint32_t* r, uint32_t a) {
    asm volatile("ldmatrix.sync.aligned.m8n8.x4.shared.b16 {%0,%1,%2,%3}, [%4];"
        : "=r"(r[0]), "=r"(r[1]), "=r"(r[2]), "=r"(r[3]) : "r"(a));
}
__device__ __forceinline__ void mma16816(float* c, const uint32_t* a, const uint32_t* b) {
    asm volatile("mma.sync.aligned.m16n8k16.row.col.f32.bf16.bf16.f32 "
        "{%0,%1,%2,%3}, {%4,%5,%6,%7}, {%8,%9}, {%0,%1,%2,%3};"
        : "+f"(c[0]), "+f"(c[1]), "+f"(c[2]), "+f"(c[3])
        : "r"(a[0]), "r"(a[1]), "r"(a[2]), "r"(a[3]), "r"(b[0]), "r"(b[1]));
}
__device__ __forceinline__ void split_bf16(float v, __nv_bfloat16& hi, __nv_bfloat16& lo) {
    hi = __float2bfloat16(v);
    lo = __float2bfloat16(v - __bfloat162float(hi));
}
__device__ __forceinline__ float join_bf16(__nv_bfloat16 hi, __nv_bfloat16 lo) {
    return __bfloat162float(hi) + __bfloat162float(lo);
}

// ---------------- mma.sync GEMM (2 CTAs/SM, single-sync 3-stage) ----------------
// 256 threads, 8 warps 4(M)x2(N), warp tile 32x48 — measured optimum (856 us).
#define ASTR 80
#define A_BYTES 10240
#define W_BYTES 7680
#define STAGE_B 35840
#define NSTAGE 3

__global__ void __launch_bounds__(256, 2) mma_gemm_kernel(
    const __nv_bfloat16* __restrict__ Ahi, const __nv_bfloat16* __restrict__ Alo,
    const __nv_bfloat16* __restrict__ Whi, const __nv_bfloat16* __restrict__ Wlo,
    const float* __restrict__ bias, int relu,
    float* __restrict__ outF, __nv_bfloat16* __restrict__ outHi, __nv_bfloat16* __restrict__ outLo,
    int Kpad, int Klog, int Nlog, int padKout)
{
    extern __shared__ __align__(128) char smem[];
    const uint32_t sb = smem_u32(smem);
    const int tid = threadIdx.x, lane = tid & 31, wid = tid >> 5;
    const int wm = wid & 3, wn = wid >> 2;
    const int m0 = blockIdx.y * 128;
    const int bn0w = blockIdx.x * 96;
    const int nch = (Klog + 31) >> 5;
    const int kstot = (Klog + 15) >> 4;

    float acc[2][6][4];
#pragma unroll
    for (int i = 0; i < 2; i++)
#pragma unroll
        for (int j = 0; j < 6; j++)
#pragma unroll
            for (int e = 0; e < 4; e++) acc[i][j][e] = 0.f;

    auto issue = [&](int c) {
        uint32_t st = sb + (uint32_t)(c % NSTAGE) * STAGE_B;
        int gk = c * 32;
#pragma unroll
        for (int i = 0; i < 4; i++) {
            int qq = tid + i * 256;
            int buf = qq >> 9, rem = qq & 511, row = rem >> 2, ch = rem & 3;
            const __nv_bfloat16* g = (buf ? Alo : Ahi) + (size_t)(m0 + row) * Kpad + gk + ch * 8;
            cpa16(st + (uint32_t)buf * A_BYTES + row * ASTR + ch * 16, g);
        }
#pragma unroll
        for (int i = 0; i < 3; i++) {
            int qq = tid + i * 256;
            int buf = qq / 384, rem = qq - buf * 384, row = rem >> 2, ch = rem & 3;
            const __nv_bfloat16* g = (buf ? Wlo : Whi) + (size_t)(bn0w + row) * Kpad + gk + ch * 8;
            cpa16(st + 2 * A_BYTES + (uint32_t)buf * W_BYTES + row * ASTR + ch * 16, g);
        }
        CP_COMMIT();
    };

    issue(0);
    if (nch > 1) issue(1);

    const int arow = wm * 32 + (lane & 15);
    const uint32_t acolb = ((lane >> 4) * 8) * 2;
    const int brow = wn * 48 + (lane & 7) + ((lane >> 4) & 1) * 8;
    const uint32_t bcolb = (((lane >> 3) & 1) * 8) * 2;

    for (int c = 0; c < nch; c++) {
        uint32_t st = sb + (uint32_t)(c % NSTAGE) * STAGE_B;
        if (c + 1 < nch) { CP_WAIT1(); } else { CP_WAIT0(); }
        __syncthreads();
        if (c + 2 < nch) issue(c + 2);
        const uint32_t aHiB = st + arow * ASTR;
        const uint32_t aLoB = aHiB + A_BYTES;
        const uint32_t wHiB = st + 2 * A_BYTES + brow * ASTR;
        const uint32_t wLoB = wHiB + W_BYTES;
#pragma unroll
        for (int ks = 0; ks < 2; ks++) {
            if (c * 2 + ks >= kstot) break;
            const uint32_t ka = acolb + ks * 32;
            const uint32_t kb = bcolb + ks * 32;
            uint32_t ah[8], al[8], bh[12], bl[12];
            ldsm4(ah,     aHiB + ka);
            ldsm4(ah + 4, aHiB + 16 * ASTR + ka);
            ldsm4(al,     aLoB + ka);
            ldsm4(al + 4, aLoB + 16 * ASTR + ka);
#pragma unroll
            for (int p = 0; p < 3; p++) {
                ldsm4(bh + 4 * p, wHiB + p * 16 * ASTR + kb);
                ldsm4(bl + 4 * p, wLoB + p * 16 * ASTR + kb);
            }
#pragma unroll
            for (int mi = 0; mi < 2; mi++)
#pragma unroll
                for (int ni = 0; ni < 6; ni++) {
                    mma16816(acc[mi][ni], ah + 4 * mi, bh + 2 * ni);
                    mma16816(acc[mi][ni], al + 4 * mi, bh + 2 * ni);
                    mma16816(acc[mi][ni], ah + 4 * mi, bl + 2 * ni);
                }
        }
    }

    const __nv_bfloat16 bz = __float2bfloat16(0.f);
#pragma unroll
    for (int mi = 0; mi < 2; mi++)
#pragma unroll
        for (int ni = 0; ni < 6; ni++) {
            int r0 = m0 + wm * 32 + mi * 16 + (lane >> 2);
            int col = bn0w + wn * 48 + ni * 8 + ((lane & 3) << 1);
#pragma unroll
            for (int e = 0; e < 4; e++) {
                int rr = r0 + (e >> 1) * 8;
                int cc = col + (e & 1);
                if (cc < Nlog) {
                    float vv = acc[mi][ni][e];
                    if (bias) vv += bias[cc];
                    if (relu) vv = fmaxf(vv, 0.f);
                    if (outF) outF[(size_t)rr * Nlog + cc] = vv;
                    if (outHi) {
                        __nv_bfloat16 hi, lo; split_bf16(vv, hi, lo);
                        outHi[(size_t)rr * padKout + cc] = hi;
                        outLo[(size_t)rr * padKout + cc] = lo;
                    }
                } else if (outHi && cc < padKout) {
                    outHi[(size_t)rr * padKout + cc] = bz;
                    outLo[(size_t)rr * padKout + cc] = bz;
                }
            }
        }
}

// ---------------- presum node tables ----------------
__global__ void __launch_bounds__(256) presum_kernel(const float* __restrict__ a,
                                                     const float* __restrict__ b,
                                                     float* __restrict__ o, size_t n4)
{
    size_t i = (size_t)blockIdx.x * blockDim.x + threadIdx.x;
    size_t st = (size_t)gridDim.x * blockDim.x;
    const float4* a4 = (const float4*)a;
    const float4* b4 = (const float4*)b;
    float4* o4 = (float4*)o;
    for (; i < n4; i += st) {
        float4 x = a4[i], y = b4[i];
        o4[i] = make_float4(x.x + y.x, x.y + y.y, x.z + y.z, x.w + y.w);
    }
}

// ---------------- weight transpose+split for m1/m2 ----------------
struct WJob { const float* src; __nv_bfloat16* hi; __nv_bfloat16* lo; int Kd, N, Kpad; };
struct WJobs { WJob j[4]; };

__global__ void __launch_bounds__(1024) wconv_all(WJobs jobs) {
    WJob jb = jobs.j[blockIdx.z];
    int k0 = blockIdx.x * 32, n0 = blockIdx.y * 32;
    if (k0 >= jb.Kpad) return;
    __shared__ float t[32][33];
    int tx = threadIdx.x, ty = threadIdx.y;
    float v = 0.f;
    if (k0 + ty < jb.Kd && n0 + tx < jb.N)
        v = jb.src[(size_t)(k0 + ty) * jb.N + n0 + tx];
    t[ty][tx] = v;
    __syncthreads();
    int n = n0 + ty, k = k0 + tx;
    if (n < HPAD && k < jb.Kpad) {
        __nv_bfloat16 h, l; split_bf16(t[tx][ty], h, l);
        jb.hi[(size_t)n * jb.Kpad + k] = h;
        jb.lo[(size_t)n * jb.Kpad + k] = l;
    }
}

// ---------------- merged folded-weight precompute ----------------
// z in 0..1: Wqk layer z;  z in 2..3: Wvo layer z-2. Layer stride = 2*plane.
__global__ void __launch_bounds__(256) wfold_build(
    const float* __restrict__ Wq, const float* __restrict__ Wk,
    const float* __restrict__ Wv, const float* __restrict__ Wo,
    __nv_bfloat16* __restrict__ qkhi, __nv_bfloat16* __restrict__ qklo,
    __nv_bfloat16* __restrict__ vohi, __nv_bfloat16* __restrict__ volo)
{
    extern __shared__ float ps[];
    float* As = ps;
    float* Bs = ps + 64 * 137;
    int z = blockIdx.z;
    int tx = threadIdx.x & 15, ty = threadIdx.x >> 4;

    if (z < 2) {
        if (blockIdx.x >= QPAD / 64) return;
        int l = z;
        const float* wq = Wq + (size_t)l * QD * QD;
        const float* wk = Wk + (size_t)l * KDd * QD;
        __nv_bfloat16* hi = qkhi + (size_t)l * (2 * QKN * QPAD);
        __nv_bfloat16* lo = qklo + (size_t)l * (2 * QKN * QPAD);
        int kb = blockIdx.x * 64, nb = blockIdx.y * 64;
        int h = nb / 448;
        for (int e = threadIdx.x; e < 64 * 136; e += 256) {
            int nl = e / 136, d = e - nl * 136;
            int dp = nb + nl - h * 448;
            float v = 0.f;
            if (h < 2 && dp < 444) v = wk[(size_t)dp * 272 + h * 136 + d];
            As[nl * 137 + d] = v;
        }
        for (int e = threadIdx.x; e < 64 * 136; e += 256) {
            int kl = e / 136, d = e - kl * 136;
            int k = kb + kl;
            float v = 0.f;
            if (h < 2 && k < 272) v = wq[(size_t)k * 272 + h * 136 + d];
            Bs[kl * 137 + d] = v;
        }
        __syncthreads();
        float acc[4][4] = {};
        for (int d = 0; d < 136; d++) {
            float a[4], b[4];
#pragma unroll
            for (int i = 0; i < 4; i++) a[i] = As[(ty * 4 + i) * 137 + d];
#pragma unroll
            for (int j = 0; j < 4; j++) b[j] = Bs[(tx * 4 + j) * 137 + d];
#pragma unroll
            for (int i = 0; i < 4; i++)
#pragma unroll
                for (int j = 0; j < 4; j++) acc[i][j] += a[i] * b[j];
        }
#pragma unroll
        for (int i = 0; i < 4; i++)
#pragma unroll
            for (int j = 0; j < 4; j++) {
                int n = nb + ty * 4 + i, k = kb + tx * 4 + j;
                __nv_bfloat16 hh, ll; split_bf16(acc[i][j], hh, ll);
                hi[(size_t)n * QPAD + k] = hh;
                lo[(size_t)n * QPAD + k] = ll;
            }
    } else {
        if (blockIdx.y >= 5) return;
        int l = z - 2;
        const float* wv = Wv + (size_t)l * KDd * QD;
        const float* wo = Wo + (size_t)l * QD * QD;
        __nv_bfloat16* hi = vohi + (size_t)l * (2 * 288 * WSP);
        __nv_bfloat16* lo = volo + (size_t)l * (2 * 288 * WSP);
        int kkb = blockIdx.x * 64, nb = blockIdx.y * 64;
        int h = kkb / 448;
        for (int e = threadIdx.x; e < 64 * 136; e += 256) {
            int kl = e / 136, d = e - kl * 136;
            int dp = kkb + kl - h * 448;
            float v = 0.f;
            if (dp < 444) v = wv[(size_t)dp * 272 + h * 136 + d];
            As[kl * 137 + d] = v;
        }
        for (int e = threadIdx.x; e < 64 * 136; e += 256) {
            int d = e >> 6, nl = e & 63;
            int n = nb + nl;
            float v = 0.f;
            if (n < 272) v = wo[(size_t)(h * 136 + d) * 272 + n];
            Bs[nl * 137 + d] = v;
        }
        __syncthreads();
        float acc[4][4] = {};
        for (int d = 0; d < 136; d++) {
            float a[4], b[4];
#pragma unroll
            for (int i = 0; i < 4; i++) a[i] = As[(ty * 4 + i) * 137 + d];
#pragma unroll
            for (int j = 0; j < 4; j++) b[j] = Bs[(tx * 4 + j) * 137 + d];
#pragma unroll
            for (int i = 0; i < 4; i++)
#pragma unroll
                for (int j = 0; j < 4; j++) acc[i][j] += a[i] * b[j];
        }
#pragma unroll
        for (int i = 0; i < 4; i++)
#pragma unroll
            for (int j = 0; j < 4; j++) {
                int kk = kkb + ty * 4 + i, n = nb + tx * 4 + j;
                if (n < 288) {
                    __nv_bfloat16 hh, ll; split_bf16(acc[i][j], hh, ll);
                    hi[(size_t)n * WSP + kk] = hh;
                    lo[(size_t)n * WSP + kk] = ll;
                }
            }
    }
}

// qk_bias[l][n] = sum_{j<DT} cos(time_b[j]) * Wqkt[l][n][DN+j]
__global__ void __launch_bounds__(128) qkbias_build(const __nv_bfloat16* __restrict__ hi,
                                                    const __nv_bfloat16* __restrict__ lo,
                                                    const float* __restrict__ time_b,
                                                    float* __restrict__ bias, size_t lstride)
{
    int n = blockIdx.x, l = blockIdx.y;
    const __nv_bfloat16* ph = hi + (size_t)l * lstride + (size_t)n * QPAD + DN;
    const __nv_bfloat16* pl = lo + (size_t)l * lstride + (size_t)n * QPAD + DN;
    __shared__ float red[4];
    int tid = threadIdx.x;
    float s = 0.f;
    for (int j = tid; j < 100; j += 128)
        s += cosf(time_b[j]) * (__bfloat162float(ph[j]) + __bfloat162float(pl[j]));
#pragma unroll
    for (int o = 16; o; o >>= 1) s += __shfl_xor_sync(0xffffffffu, s, o);
    if ((tid & 31) == 0) red[tid >> 5] = s;
    __syncthreads();
    if (tid == 0)
        bias[(size_t)l * WSP + n] = red[0] + red[1] + red[2] + red[3];
}

// ---------------- feature builds ----------------
__global__ void build_nf_qin(const int* __restrict__ idsA, const int* __restrict__ idsB, int nA,
                             const float* __restrict__ memories, const float* __restrict__ node_raw,
                             __nv_bfloat16* __restrict__ qhi, __nv_bfloat16* __restrict__ qlo)
{
    int m = blockIdx.x;
    int id = (m < nA) ? idsA[m] : idsB[m - nA];
    for (int j = threadIdx.x; j < QPAD; j += blockDim.x) {
        float v = (j < DN) ? memories[(size_t)id * DN + j] + node_raw[(size_t)id * DN + j] : 0.f;
        __nv_bfloat16 h, l; split_bf16(v, h, l);
        qhi[(size_t)m * QPAD + j] = h;
        qlo[(size_t)m * QPAD + j] = l;
    }
}

__global__ void build_qin_conv(const float* __restrict__ conv,
                               __nv_bfloat16* __restrict__ qhi, __nv_bfloat16* __restrict__ qlo)
{
    int m = blockIdx.x;
    for (int j = threadIdx.x; j < QPAD; j += blockDim.x) {
        float v = (j < DN) ? conv[(size_t)m * DN + j] : 0.f;
        __nv_bfloat16 h, l; split_bf16(v, h, l);
        qhi[(size_t)m * QPAD + j] = h;
        qlo[(size_t)m * QPAD + j] = l;
    }
}

// ---------------- fused kv-build + attention + weighted-sum ----------------
// Two-head fused loops: each kv smem read feeds both heads.
__global__ void __launch_bounds__(256) attn_fused(
    const float* __restrict__ qk,
    const float* __restrict__ feat,          // null -> gather nsum
    const int* __restrict__ idsA, const int* __restrict__ eidsA,
    const float* __restrict__ tA, const float* __restrict__ ntA, int nA,
    const int* __restrict__ idsB, const int* __restrict__ eidsB,
    const float* __restrict__ tB, const float* __restrict__ ntB,
    const float* __restrict__ nsum, const float* __restrict__ edge_raw,
    const float* __restrict__ time_w, const float* __restrict__ time_b,
    __nv_bfloat16* __restrict__ wshi, __nv_bfloat16* __restrict__ wslo)
{
    const float SCALE = 0.08574929257125442f;   // 136^-0.5
    __shared__ __align__(16) float kvs[Kn][KVPAD];
    __shared__ __align__(16) float qks[WSP];
    __shared__ float att[2 * Kn];
    __shared__ int   sids[Kn];

    int m = blockIdx.x;
    int tid = threadIdx.x, wid = tid >> 5, lane = tid & 31;
    const uint32_t kvs_b = smem_u32(kvs);

    const int* nbr_ids; const int* nbr_eids; const float* nbr_t; float tm;
    if (m < nA) {
        nbr_ids = idsA + (size_t)m * Kn;
        nbr_eids = eidsA + (size_t)m * Kn;
        nbr_t = ntA + (size_t)m * Kn;
        tm = tA[m];
    } else {
        int mm = m - nA;
        nbr_ids = idsB + (size_t)mm * Kn;
        nbr_eids = eidsB + (size_t)mm * Kn;
        nbr_t = ntB + (size_t)mm * Kn;
        tm = tB[mm];
    }

    if (tid < Kn) sids[tid] = nbr_ids[tid];
    if (tid < 224)
        cpa16(smem_u32(qks) + tid * 16, (const float4*)(qk + (size_t)m * WSP) + tid);

    for (int p = wid; p < Kn; p += 8) {
        int nid = nbr_ids[p];
        int eid = nbr_eids[p];
        const float4* nsrc = feat ? (const float4*)(feat + ((size_t)m * Kn + p) * DN)
                                  : (const float4*)(nsum + (size_t)nid * DN);
        const float4* esrc = (const float4*)(edge_raw + (size_t)eid * DE);
        uint32_t dst = kvs_b + (uint32_t)p * (KVPAD * 4);
#pragma unroll
        for (int it = 0; it < 3; it++) {
            int ch = lane + it * 32;
            if (ch < 86) {
                if (ch < 43) cpa16(dst + ch * 16, nsrc + ch);
                else         cpa16(dst + 688 + (ch - 43) * 16, esrc + (ch - 43));
            }
        }
        float dt = __fadd_rn(tm, -nbr_t[p]);
#pragma unroll
        for (int it = 0; it < 4; it++) {
            int j = lane + it * 32;
            if (j < 100)
                kvs[p][344 + j] = cosf(__fadd_rn(__fmul_rn(dt, time_w[j]), time_b[j]));
        }
        if (lane < 4) kvs[p][444 + lane] = 0.f;
    }
    CP_COMMIT();
    CP_WAIT0();
    __syncthreads();

    // scores: kk-major, both heads in one pass over the kv row
    for (int kk = wid; kk < Kn; kk += 8) {
        float s0 = 0.f, s1 = 0.f;
        for (int d = lane; d < KDd; d += 32) {
            float v = kvs[kk][d];
            s0 += qks[d] * v;
            s1 += qks[448 + d] * v;
        }
#pragma unroll
        for (int o = 16; o; o >>= 1) {
            s0 += __shfl_xor_sync(0xffffffffu, s0, o);
            s1 += __shfl_xor_sync(0xffffffffu, s1, o);
        }
        if (lane == 0) {
            bool msk = (sids[kk] == 0);
            att[kk]      = msk ? -1e10f : s0 * SCALE;
            att[Kn + kk] = msk ? -1e10f : s1 * SCALE;
        }
    }
    __syncthreads();

    if (tid < 2) {
        int h = tid;
        float mx = -INFINITY;
        for (int kk = 0; kk < Kn; kk++) mx = fmaxf(mx, att[h * Kn + kk]);
        float sum = 0.f;
        for (int kk = 0; kk < Kn; kk++) { float e = expf(att[h*Kn+kk] - mx); att[h*Kn+kk] = e; sum += e; }
        float inv = 1.f / sum;
        for (int kk = 0; kk < Kn; kk++) att[h * Kn + kk] *= inv;
    }
    __syncthreads();

    // weighted sums: one kv read feeds both heads
    for (int jj = tid; jj < 448; jj += 256) {
        float a0 = 0.f, a1 = 0.f;
#pragma unroll
        for (int kk = 0; kk < Kn; kk++) {
            float v = kvs[kk][jj];
            a0 += att[kk] * v;
            a1 += att[Kn + kk] * v;
        }
        __nv_bfloat16 h0, l0, h1, l1;
        split_bf16(a0, h0, l0);
        split_bf16(a1, h1, l1);
        wshi[(size_t)m * WSP + jj] = h0;
        wslo[(size_t)m * WSP + jj] = l0;
        wshi[(size_t)m * WSP + 448 + jj] = h1;
        wslo[(size_t)m * WSP + 448 + jj] = l1;
    }
}

// ---------------- residual + bias + LayerNorm + cat (hi/lo residual reconstruction) ---
__global__ void lncat_kernel(const float* __restrict__ o, const float* __restrict__ bo,
                             const __nv_bfloat16* __restrict__ resHi, const __nv_bfloat16* __restrict__ resLo,
                             const __nv_bfloat16* __restrict__ nfHi, const __nv_bfloat16* __restrict__ nfLo,
                             const float* __restrict__ time_b,
                             const float* __restrict__ gam, const float* __restrict__ bet,
                             __nv_bfloat16* __restrict__ chi, __nv_bfloat16* __restrict__ clo)
{
    int m = blockIdx.x;
    int tid = threadIdx.x;
    __shared__ float buf[QD];
    __shared__ float red[32];
    for (int j = tid; j < QD; j += 256) {
        float res = (j < DN)
            ? join_bf16(resHi[(size_t)m * QPAD + j], resLo[(size_t)m * QPAD + j])
            : cosf(time_b[j - DN]);
        buf[j] = o[(size_t)m * QD + j] + bo[j] + res;
    }
    __syncthreads();
    float s = 0.f;
    for (int j = tid; j < QD; j += 256) s += buf[j];
#pragma unroll
    for (int off = 16; off; off >>= 1) s += __shfl_xor_sync(0xffffffffu, s, off);
    if ((tid & 31) == 0) red[tid >> 5] = s;
    __syncthreads();
    if (tid < 32) {
        float t = (tid < 8) ? red[tid] : 0.f;
#pragma unroll
        for (int off = 4; off; off >>= 1) t += __shfl_xor_sync(0xffffffffu, t, off);
        if (tid == 0) red[0] = t;
    }
    __syncthreads();
    float mu = red[0] / (float)QD;
    __syncthreads();
    float s2 = 0.f;
    for (int j = tid; j < QD; j += 256) { float d = buf[j] - mu; s2 += d * d; }
#pragma unroll
    for (int off = 16; off; off >>= 1) s2 += __shfl_xor_sync(0xffffffffu, s2, off);
    if ((tid & 31) == 0) red[tid >> 5] = s2;
    __syncthreads();
    if (tid < 32) {
        float t = (tid < 8) ? red[tid] : 0.f;
#pragma unroll
        for (int off = 4; off; off >>= 1) t += __shfl_xor_sync(0xffffffffu, t, off);
        if (tid == 0) red[0] = t;
    }
    __syncthreads();
    float var = red[0] / (float)QD;
    float rinv = 1.0f / sqrtf(var + 1e-5f);
    for (int j = tid; j < KVPAD; j += 256) {
        float vv;
        if (j < QD)
            vv = (buf[j] - mu) * rinv * gam[j] + bet[j];
        else if (j < KDd)
            vv = join_bf16(nfHi[(size_t)m * QPAD + (j - QD)], nfLo[(size_t)m * QPAD + (j - QD)]);
        else
            vv = 0.f;
        __nv_bfloat16 hi, lo; split_bf16(vv, hi, lo);
        chi[(size_t)m * KVPAD + j] = hi;
        clo[(size_t)m * KVPAD + j] = lo;
    }
}

// ---------------- host ----------------
extern "C" void kernel_launch(void* const* d_in, const int* in_sizes, int n_in,
                              void* d_out, int out_size)
{
    (void)in_sizes; (void)n_in; (void)out_size;
    const float* node_raw = (const float*)d_in[0];
    const float* edge_raw = (const float*)d_in[1];
    const float* memories = (const float*)d_in[2];
    const float* t_node   = (const float*)d_in[3];
    const float* t_n1     = (const float*)d_in[4];
    const float* t_n2     = (const float*)d_in[5];
    const float* time_w   = (const float*)d_in[6];
    const float* time_b   = (const float*)d_in[7];
    const float* Wq       = (const float*)d_in[8];
    const float* Wk       = (const float*)d_in[9];
    const float* Wv       = (const float*)d_in[10];
    const float* Wo       = (const float*)d_in[11];
    const float* bo       = (const float*)d_in[12];
    const float* ln_g     = (const float*)d_in[13];
    const float* ln_b     = (const float*)d_in[14];
    const float* m_w1     = (const float*)d_in[15];
    const float* m_b1     = (const float*)d_in[16];
    const float* m_w2     = (const float*)d_in[17];
    const float* m_b2     = (const float*)d_in[18];
    const int* node_ids   = (const int*)d_in[19];
    const int* n1_ids     = (const int*)d_in[20];
    const int* n1_eids    = (const int*)d_in[21];
    const int* n2_ids     = (const int*)d_in[22];
    const int* n2_eids    = (const int*)d_in[23];
    float* out = (float*)d_out;

    float *nsum, *qkbuf, *obuf, *conv, *qkbias;
    __nv_bfloat16 *qin_hi, *qin_lo, *ws_hi, *ws_lo, *cat_hi, *cat_lo, *h_hi, *h_lo;
    __nv_bfloat16 *wqkt, *wvot, *w1t, *w2t;
    cudaGetSymbolAddress((void**)&nsum, g_nsum);
    cudaGetSymbolAddress((void**)&qkbuf, g_qk);
    cudaGetSymbolAddress((void**)&obuf, g_o);
    cudaGetSymbolAddress((void**)&conv, g_conv);
    cudaGetSymbolAddress((void**)&qkbias, g_qkbias);
    cudaGetSymbolAddress((void**)&qin_hi, g_qin_hi);
    cudaGetSymbolAddress((void**)&qin_lo, g_qin_lo);
    cudaGetSymbolAddress((void**)&ws_hi, g_ws_hi);
    cudaGetSymbolAddress((void**)&ws_lo, g_ws_lo);
    cudaGetSymbolAddress((void**)&cat_hi, g_cat_hi);
    cudaGetSymbolAddress((void**)&cat_lo, g_cat_lo);
    cudaGetSymbolAddress((void**)&h_hi, g_h_hi);
    cudaGetSymbolAddress((void**)&h_lo, g_h_lo);
    cudaGetSymbolAddress((void**)&wqkt, g_wqkt);
    cudaGetSymbolAddress((void**)&wvot, g_wvot);
    cudaGetSymbolAddress((void**)&w1t, g_w1t);
    cudaGetSymbolAddress((void**)&w2t, g_w2t);

    cudaFuncSetAttribute(mma_gemm_kernel, cudaFuncAttributeMaxDynamicSharedMemorySize, NSTAGE * STAGE_B);
    cudaFuncSetAttribute(wfold_build, cudaFuncAttributeMaxDynamicSharedMemorySize, 2 * 64 * 137 * 4);

    auto wpq = [&](int l, int hl) { return wqkt + ((size_t)(l * 2 + hl)) * (QKN * QPAD); };
    auto wpv = [&](int l, int hl) { return wvot + ((size_t)(l * 2 + hl)) * (288 * WSP); };
    auto wp1 = [&](int l, int hl) { return w1t + ((size_t)(l * 2 + hl)) * (HPAD * KVPAD); };
    auto wp2 = [&](int l, int hl) { return w2t + ((size_t)(l * 2 + hl)) * (HPAD * HPAD); };

    auto rungemm = [&](const __nv_bfloat16* aH, const __nv_bfloat16* aL,
                       const __nv_bfloat16* wH, const __nv_bfloat16* wL,
                       const float* bias, int relu, float* oF,
                       __nv_bfloat16* oH, __nv_bfloat16* oL,
                       int M, int Kpad, int Klog, int Nlog, int padKout) {
        dim3 grid((Nlog + 95) / 96, M / 128);
        mma_gemm_kernel<<<grid, 256, NSTAGE * STAGE_B>>>(aH, aL, wH, wL, bias, relu,
                                                         oF, oH, oL, Kpad, Klog, Nlog, padKout);
    };

    // 1: wfold  2: qkbias  3: build_nf  4: qk GEMM (profiled)
    wfold_build<<<dim3(WSP/64, QKN/64, 4), 256, 2*64*137*4>>>(
        Wq, Wk, Wv, Wo, wpq(0,0), wpq(0,1), wpv(0,0), wpv(0,1));
    qkbias_build<<<dim3(WSP, 2), 128>>>(wpq(0,0), wpq(0,1), time_b, qkbias,
                                        (size_t)2 * QKN * QPAD);
    build_nf_qin<<<MT, 256>>>(n1_ids, node_ids, M2, memories, node_raw, qin_hi, qin_lo);
    rungemm(qin_hi, qin_lo, wpq(0,0), wpq(0,1), qkbias, 0,
            qkbuf, nullptr, nullptr, MT, QPAD, DN, WSP, 0);
    presum_kernel<<<8192, 256>>>(memories, node_raw, nsum, (size_t)NNODE * DN / 4);
    WJobs jobs;
    for (int l = 0; l < 2; l++) {
        jobs.j[l*2+0] = { m_w1 + (size_t)l*KDd*DN, wp1(l,0), wp1(l,1), KDd, DN, KVPAD };
        jobs.j[l*2+1] = { m_w2 + (size_t)l*DN*DN,  wp2(l,0), wp2(l,1), DN,  DN, HPAD  };
    }
    wconv_all<<<dim3(KVPAD/32, HPAD/32, 4), dim3(32, 32)>>>(jobs);

    // ---- phase A+B tail ----
    attn_fused<<<MT, 256>>>(qkbuf, nullptr, n2_ids, n2_eids, t_n1, t_n2, M2,
                            n1_ids, n1_eids, t_node, t_n1,
                            nsum, edge_raw, time_w, time_b, ws_hi, ws_lo);
    rungemm(ws_hi, ws_lo, wpv(0,0), wpv(0,1), nullptr, 0,
            obuf, nullptr, nullptr, MT, WSP, WSP, QD, 0);
    lncat_kernel<<<MT, 256>>>(obuf, bo, qin_hi, qin_lo, qin_hi, qin_lo, time_b,
                              ln_g, ln_b, cat_hi, cat_lo);
    rungemm(cat_hi, cat_lo, wp1(0,0), wp1(0,1), m_b1, 1,
            nullptr, h_hi, h_lo, MT, KVPAD, KVPAD, DN, HPAD);
    rungemm(h_hi, h_lo, wp2(0,0), wp2(0,1), m_b2, 0,
            conv, nullptr, nullptr, MT, HPAD, DN, DN, 0);

    // ---- phase C: layer 1 over center nodes ----
    build_qin_conv<<<Bsz, 256>>>(conv + (size_t)M2 * DN, qin_hi, qin_lo);
    rungemm(qin_hi, qin_lo, wpq(1,0), wpq(1,1), qkbias + WSP, 0,
            qkbuf, nullptr, nullptr, Bsz, QPAD, DN, WSP, 0);
    attn_fused<<<Bsz, 256>>>(qkbuf, conv, n1_ids, n1_eids, t_node, t_n1, Bsz,
                             n1_ids, n1_eids, t_node, t_n1,
                             nsum, edge_raw, time_w, time_b, ws_hi, ws_lo);
    rungemm(ws_hi, ws_lo, wpv(1,0), wpv(1,1), nullptr, 0,
            obuf, nullptr, nullptr, Bsz, WSP, WSP, QD, 0);
    lncat_kernel<<<Bsz, 256>>>(obuf, bo + QD, qin_hi, qin_lo,
                               qin_hi + (size_t)M2 * QPAD, qin_lo + (size_t)M2 * QPAD,
                               time_b, ln_g + QD, ln_b + QD, cat_hi, cat_lo);
    rungemm(cat_hi, cat_lo, wp1(1,0), wp1(1,1), m_b1 + DN, 1,
            nullptr, h_hi, h_lo, Bsz, KVPAD, KVPAD, DN, HPAD);
    rungemm(h_hi, h_lo, wp2(1,0), wp2(1,1), m_b2 + DN, 0,
            out, nullptr, nullptr, Bsz, HPAD, DN, DN, 0);
}

// round 17
// speedup vs baseline: 1.0892x; 1.0076x over previous
#include <cuda_runtime.h>
#include <cuda_bf16.h>
#include <math.h>
#include <stdint.h>

#define Bsz 1024
#define Kn  20
#define DN  172
#define DE  172
#define QD  272
#define KDd 444
#define M2  (Bsz*Kn)      // 20480
#define MT  (M2+Bsz)      // 21504 = 168*128
#define QPAD  192         // qin K-pad (time part folded into qkbias)
#define WKP   320         // wqkt K-stride (keeps time cols 172..271 for bias)
#define KVPAD 448
#define HPAD  192
#define WSP   896   // packed 2 heads x 448
#define QKN   960
#define NNODE 100001
#define PBLK  4096  // presum blocks appended to build_nf grid

// ---------------- device scratch ----------------
__device__ __align__(128) float g_nsum[(size_t)NNODE*DN];
__device__ __align__(128) float g_qk[(size_t)MT*WSP];
__device__ __align__(128) __nv_bfloat16 g_ws_hi[(size_t)MT*WSP];
__device__ __align__(128) __nv_bfloat16 g_ws_lo[(size_t)MT*WSP];
__device__ __align__(128) float g_o[(size_t)MT*QD];
__device__ __align__(128) __nv_bfloat16 g_qin_hi[(size_t)MT*QPAD];
__device__ __align__(128) __nv_bfloat16 g_qin_lo[(size_t)MT*QPAD];
__device__ __align__(128) __nv_bfloat16 g_cat_hi[(size_t)MT*KVPAD];
__device__ __align__(128) __nv_bfloat16 g_cat_lo[(size_t)MT*KVPAD];
__device__ __align__(128) __nv_bfloat16 g_h_hi[(size_t)MT*HPAD];
__device__ __align__(128) __nv_bfloat16 g_h_lo[(size_t)MT*HPAD];
__device__ __align__(128) float g_conv[(size_t)MT*DN];
__device__ __align__(128) float g_qkbias[2*WSP];
__device__ __align__(128) __nv_bfloat16 g_wqkt[2][2][QKN*WKP];
__device__ __align__(128) __nv_bfloat16 g_wvot[2][2][288*WSP];
__device__ __align__(128) __nv_bfloat16 g_w1t[2][2][HPAD*KVPAD];
__device__ __align__(128) __nv_bfloat16 g_w2t[2][2][HPAD*HPAD];

// ---------------- helpers ----------------
__device__ __forceinline__ uint32_t smem_u32(const void* p) {
    uint32_t a;
    asm("{ .reg .u64 t; cvta.to.shared.u64 t, %1; cvt.u32.u64 %0, t; }" : "=r"(a) : "l"(p));
    return a;
}
__device__ __forceinline__ void cpa16(uint32_t s, const void* g) {
    asm volatile("cp.async.cg.shared.global [%0], [%1], 16;" :: "r"(s), "l"(g));
}
#define CP_COMMIT() asm volatile("cp.async.commit_group;" ::: "memory")
#define CP_WAIT1()  asm volatile("cp.async.wait_group 1;" ::: "memory")
#define CP_WAIT0()  asm volatile("cp.async.wait_group 0;" ::: "memory")

__device__ __forceinline__ void ldsm4(uint32_t* r, uint32_t a) {
    asm volatile("ldmatrix.sync.aligned.m8n8.x4.shared.b16 {%0,%1,%2,%3}, [%4];"
        : "=r"(r[0]), "=r"(r[1]), "=r"(r[2]), "=r"(r[3]) : "r"(a));
}
__device__ __forceinline__ void mma16816(float* c, const uint32_t* a, const uint32_t* b) {
    asm volatile("mma.sync.aligned.m16n8k16.row.col.f32.bf16.bf16.f32 "
        "{%0,%1,%2,%3}, {%4,%5,%6,%7}, {%8,%9}, {%0,%1,%2,%3};"
        : "+f"(c[0]), "+f"(c[1]), "+f"(c[2]), "+f"(c[3])
        : "r"(a[0]), "r"(a[1]), "r"(a[2]), "r"(a[3]), "r"(b[0]), "r"(b[1]));
}
__device__ __forceinline__ void split_bf16(float v, __nv_bfloat16& hi, __nv_bfloat16& lo) {
    hi = __float2bfloat16(v);
    lo = __float2bfloat16(v - __bfloat162float(hi));
}
__device__ __forceinline__ float join_bf16(__nv_bfloat16 hi, __nv_bfloat16 lo) {
    return __bfloat162float(hi) + __bfloat162float(lo);
}

// ---------------- mma.sync GEMM (2 CTAs/SM, single-sync 3-stage) ----------------
// 256 threads, 8 warps 4(M)x2(N), warp tile 32x48 — measured optimum.
// KpadA/KpadW: separate row strides for A and W (qk GEMM: A=192, W=320).
#define ASTR 80
#define A_BYTES 10240
#define W_BYTES 7680
#define STAGE_B 35840
#define NSTAGE 3

__global__ void __launch_bounds__(256, 2) mma_gemm_kernel(
    const __nv_bfloat16* __restrict__ Ahi, const __nv_bfloat16* __restrict__ Alo,
    const __nv_bfloat16* __restrict__ Whi, const __nv_bfloat16* __restrict__ Wlo,
    const float* __restrict__ bias, int relu,
    float* __restrict__ outF, __nv_bfloat16* __restrict__ outHi, __nv_bfloat16* __restrict__ outLo,
    int KpadA, int KpadW, int Klog, int Nlog, int padKout)
{
    extern __shared__ __align__(128) char smem[];
    const uint32_t sb = smem_u32(smem);
    const int tid = threadIdx.x, lane = tid & 31, wid = tid >> 5;
    const int wm = wid & 3, wn = wid >> 2;
    const int m0 = blockIdx.y * 128;
    const int bn0w = blockIdx.x * 96;
    const int nch = (Klog + 31) >> 5;
    const int kstot = (Klog + 15) >> 4;

    float acc[2][6][4];
#pragma unroll
    for (int i = 0; i < 2; i++)
#pragma unroll
        for (int j = 0; j < 6; j++)
#pragma unroll
            for (int e = 0; e < 4; e++) acc[i][j][e] = 0.f;

    auto issue = [&](int c) {
        uint32_t st = sb + (uint32_t)(c % NSTAGE) * STAGE_B;
        int gk = c * 32;
#pragma unroll
        for (int i = 0; i < 4; i++) {
            int qq = tid + i * 256;
            int buf = qq >> 9, rem = qq & 511, row = rem >> 2, ch = rem & 3;
            const __nv_bfloat16* g = (buf ? Alo : Ahi) + (size_t)(m0 + row) * KpadA + gk + ch * 8;
            cpa16(st + (uint32_t)buf * A_BYTES + row * ASTR + ch * 16, g);
        }
#pragma unroll
        for (int i = 0; i < 3; i++) {
            int qq = tid + i * 256;
            int buf = qq / 384, rem = qq - buf * 384, row = rem >> 2, ch = rem & 3;
            const __nv_bfloat16* g = (buf ? Wlo : Whi) + (size_t)(bn0w + row) * KpadW + gk + ch * 8;
            cpa16(st + 2 * A_BYTES + (uint32_t)buf * W_BYTES + row * ASTR + ch * 16, g);
        }
        CP_COMMIT();
    };

    issue(0);
    if (nch > 1) issue(1);

    const int arow = wm * 32 + (lane & 15);
    const uint32_t acolb = ((lane >> 4) * 8) * 2;
    const int brow = wn * 48 + (lane & 7) + ((lane >> 4) & 1) * 8;
    const uint32_t bcolb = (((lane >> 3) & 1) * 8) * 2;

    for (int c = 0; c < nch; c++) {
        uint32_t st = sb + (uint32_t)(c % NSTAGE) * STAGE_B;
        if (c + 1 < nch) { CP_WAIT1(); } else { CP_WAIT0(); }
        __syncthreads();
        if (c + 2 < nch) issue(c + 2);
        const uint32_t aHiB = st + arow * ASTR;
        const uint32_t aLoB = aHiB + A_BYTES;
        const uint32_t wHiB = st + 2 * A_BYTES + brow * ASTR;
        const uint32_t wLoB = wHiB + W_BYTES;
#pragma unroll
        for (int ks = 0; ks < 2; ks++) {
            if (c * 2 + ks >= kstot) break;
            const uint32_t ka = acolb + ks * 32;
            const uint32_t kb = bcolb + ks * 32;
            uint32_t ah[8], al[8], bh[12], bl[12];
            ldsm4(ah,     aHiB + ka);
            ldsm4(ah + 4, aHiB + 16 * ASTR + ka);
            ldsm4(al,     aLoB + ka);
            ldsm4(al + 4, aLoB + 16 * ASTR + ka);
#pragma unroll
            for (int p = 0; p < 3; p++) {
                ldsm4(bh + 4 * p, wHiB + p * 16 * ASTR + kb);
                ldsm4(bl + 4 * p, wLoB + p * 16 * ASTR + kb);
            }
#pragma unroll
            for (int mi = 0; mi < 2; mi++)
#pragma unroll
                for (int ni = 0; ni < 6; ni++) {
                    mma16816(acc[mi][ni], ah + 4 * mi, bh + 2 * ni);
                    mma16816(acc[mi][ni], al + 4 * mi, bh + 2 * ni);
                    mma16816(acc[mi][ni], ah + 4 * mi, bl + 2 * ni);
                }
        }
    }

    const __nv_bfloat16 bz = __float2bfloat16(0.f);
#pragma unroll
    for (int mi = 0; mi < 2; mi++)
#pragma unroll
        for (int ni = 0; ni < 6; ni++) {
            int r0 = m0 + wm * 32 + mi * 16 + (lane >> 2);
            int col = bn0w + wn * 48 + ni * 8 + ((lane & 3) << 1);
#pragma unroll
            for (int e = 0; e < 4; e++) {
                int rr = r0 + (e >> 1) * 8;
                int cc = col + (e & 1);
                if (cc < Nlog) {
                    float vv = acc[mi][ni][e];
                    if (bias) vv += bias[cc];
                    if (relu) vv = fmaxf(vv, 0.f);
                    if (outF) outF[(size_t)rr * Nlog + cc] = vv;
                    if (outHi) {
                        __nv_bfloat16 hi, lo; split_bf16(vv, hi, lo);
                        outHi[(size_t)rr * padKout + cc] = hi;
                        outLo[(size_t)rr * padKout + cc] = lo;
                    }
                } else if (outHi && cc < padKout) {
                    outHi[(size_t)rr * padKout + cc] = bz;
                    outLo[(size_t)rr * padKout + cc] = bz;
                }
            }
        }
}

// ---------------- weight transpose+split for m1/m2 ----------------
struct WJob { const float* src; __nv_bfloat16* hi; __nv_bfloat16* lo; int Kd, N, Kpad; };
struct WJobs { WJob j[4]; };

__global__ void __launch_bounds__(1024) wconv_all(WJobs jobs) {
    WJob jb = jobs.j[blockIdx.z];
    int k0 = blockIdx.x * 32, n0 = blockIdx.y * 32;
    if (k0 >= jb.Kpad) return;
    __shared__ float t[32][33];
    int tx = threadIdx.x, ty = threadIdx.y;
    float v = 0.f;
    if (k0 + ty < jb.Kd && n0 + tx < jb.N)
        v = jb.src[(size_t)(k0 + ty) * jb.N + n0 + tx];
    t[ty][tx] = v;
    __syncthreads();
    int n = n0 + ty, k = k0 + tx;
    if (n < HPAD && k < jb.Kpad) {
        __nv_bfloat16 h, l; split_bf16(t[tx][ty], h, l);
        jb.hi[(size_t)n * jb.Kpad + k] = h;
        jb.lo[(size_t)n * jb.Kpad + k] = l;
    }
}

// ---------------- merged folded-weight precompute ----------------
// z in 0..1: Wqk layer z;  z in 2..3: Wvo layer z-2. Layer stride = 2*plane.
__global__ void __launch_bounds__(256) wfold_build(
    const float* __restrict__ Wq, const float* __restrict__ Wk,
    const float* __restrict__ Wv, const float* __restrict__ Wo,
    __nv_bfloat16* __restrict__ qkhi, __nv_bfloat16* __restrict__ qklo,
    __nv_bfloat16* __restrict__ vohi, __nv_bfloat16* __restrict__ volo)
{
    extern __shared__ float ps[];
    float* As = ps;
    float* Bs = ps + 64 * 137;
    int z = blockIdx.z;
    int tx = threadIdx.x & 15, ty = threadIdx.x >> 4;

    if (z < 2) {
        if (blockIdx.x >= WKP / 64) return;
        int l = z;
        const float* wq = Wq + (size_t)l * QD * QD;
        const float* wk = Wk + (size_t)l * KDd * QD;
        __nv_bfloat16* hi = qkhi + (size_t)l * (2 * QKN * WKP);
        __nv_bfloat16* lo = qklo + (size_t)l * (2 * QKN * WKP);
        int kb = blockIdx.x * 64, nb = blockIdx.y * 64;
        int h = nb / 448;
        for (int e = threadIdx.x; e < 64 * 136; e += 256) {
            int nl = e / 136, d = e - nl * 136;
            int dp = nb + nl - h * 448;
            float v = 0.f;
            if (h < 2 && dp < 444) v = wk[(size_t)dp * 272 + h * 136 + d];
            As[nl * 137 + d] = v;
        }
        for (int e = threadIdx.x; e < 64 * 136; e += 256) {
            int kl = e / 136, d = e - kl * 136;
            int k = kb + kl;
            float v = 0.f;
            if (h < 2 && k < 272) v = wq[(size_t)k * 272 + h * 136 + d];
            Bs[kl * 137 + d] = v;
        }
        __syncthreads();
        float acc[4][4] = {};
        for (int d = 0; d < 136; d++) {
            float a[4], b[4];
#pragma unroll
            for (int i = 0; i < 4; i++) a[i] = As[(ty * 4 + i) * 137 + d];
#pragma unroll
            for (int j = 0; j < 4; j++) b[j] = Bs[(tx * 4 + j) * 137 + d];
#pragma unroll
            for (int i = 0; i < 4; i++)
#pragma unroll
                for (int j = 0; j < 4; j++) acc[i][j] += a[i] * b[j];
        }
#pragma unroll
        for (int i = 0; i < 4; i++)
#pragma unroll
            for (int j = 0; j < 4; j++) {
                int n = nb + ty * 4 + i, k = kb + tx * 4 + j;
                __nv_bfloat16 hh, ll; split_bf16(acc[i][j], hh, ll);
                hi[(size_t)n * WKP + k] = hh;
                lo[(size_t)n * WKP + k] = ll;
            }
    } else {
        if (blockIdx.y >= 5) return;
        int l = z - 2;
        const float* wv = Wv + (size_t)l * KDd * QD;
        const float* wo = Wo + (size_t)l * QD * QD;
        __nv_bfloat16* hi = vohi + (size_t)l * (2 * 288 * WSP);
        __nv_bfloat16* lo = volo + (size_t)l * (2 * 288 * WSP);
        int kkb = blockIdx.x * 64, nb = blockIdx.y * 64;
        int h = kkb / 448;
        for (int e = threadIdx.x; e < 64 * 136; e += 256) {
            int kl = e / 136, d = e - kl * 136;
            int dp = kkb + kl - h * 448;
            float v = 0.f;
            if (dp < 444) v = wv[(size_t)dp * 272 + h * 136 + d];
            As[kl * 137 + d] = v;
        }
        for (int e = threadIdx.x; e < 64 * 136; e += 256) {
            int d = e >> 6, nl = e & 63;
            int n = nb + nl;
            float v = 0.f;
            if (n < 272) v = wo[(size_t)(h * 136 + d) * 272 + n];
            Bs[nl * 137 + d] = v;
        }
        __syncthreads();
        float acc[4][4] = {};
        for (int d = 0; d < 136; d++) {
            float a[4], b[4];
#pragma unroll
            for (int i = 0; i < 4; i++) a[i] = As[(ty * 4 + i) * 137 + d];
#pragma unroll
            for (int j = 0; j < 4; j++) b[j] = Bs[(tx * 4 + j) * 137 + d];
#pragma unroll
            for (int i = 0; i < 4; i++)
#pragma unroll
                for (int j = 0; j < 4; j++) acc[i][j] += a[i] * b[j];
        }
#pragma unroll
        for (int i = 0; i < 4; i++)
#pragma unroll
            for (int j = 0; j < 4; j++) {
                int kk = kkb + ty * 4 + i, n = nb + tx * 4 + j;
                if (n < 288) {
                    __nv_bfloat16 hh, ll; split_bf16(acc[i][j], hh, ll);
                    hi[(size_t)n * WSP + kk] = hh;
                    lo[(size_t)n * WSP + kk] = ll;
                }
            }
    }
}

// qk_bias[l][n] = sum_{j<DT} cos(time_b[j]) * Wqkt[l][n][DN+j]
__global__ void __launch_bounds__(128) qkbias_build(const __nv_bfloat16* __restrict__ hi,
                                                    const __nv_bfloat16* __restrict__ lo,
                                                    const float* __restrict__ time_b,
                                                    float* __restrict__ bias, size_t lstride)
{
    int n = blockIdx.x, l = blockIdx.y;
    const __nv_bfloat16* ph = hi + (size_t)l * lstride + (size_t)n * WKP + DN;
    const __nv_bfloat16* pl = lo + (size_t)l * lstride + (size_t)n * WKP + DN;
    __shared__ float red[4];
    int tid = threadIdx.x;
    float s = 0.f;
    for (int j = tid; j < 100; j += 128)
        s += cosf(time_b[j]) * (__bfloat162float(ph[j]) + __bfloat162float(pl[j]));
#pragma unroll
    for (int o = 16; o; o >>= 1) s += __shfl_xor_sync(0xffffffffu, s, o);
    if ((tid & 31) == 0) red[tid >> 5] = s;
    __syncthreads();
    if (tid == 0)
        bias[(size_t)l * WSP + n] = red[0] + red[1] + red[2] + red[3];
}

// ---------------- feature build + presum (merged) ----------------
// blocks < nA+nB: build qin hi/lo.  blocks >= : grid-stride presum of nsum.
__global__ void build_nf_qin(const int* __restrict__ idsA, const int* __restrict__ idsB, int nA,
                             const float* __restrict__ memories, const float* __restrict__ node_raw,
                             __nv_bfloat16* __restrict__ qhi, __nv_bfloat16* __restrict__ qlo,
                             float* __restrict__ nsum, size_t n4, int nTot)
{
    int m = blockIdx.x;
    if (m < nTot) {
        int id = (m < nA) ? idsA[m] : idsB[m - nA];
        for (int j = threadIdx.x; j < QPAD; j += blockDim.x) {
            float v = (j < DN) ? memories[(size_t)id * DN + j] + node_raw[(size_t)id * DN + j] : 0.f;
            __nv_bfloat16 h, l; split_bf16(v, h, l);
            qhi[(size_t)m * QPAD + j] = h;
            qlo[(size_t)m * QPAD + j] = l;
        }
    } else {
        size_t i = (size_t)(m - nTot) * blockDim.x + threadIdx.x;
        size_t st = (size_t)PBLK * blockDim.x;
        const float4* a4 = (const float4*)memories;
        const float4* b4 = (const float4*)node_raw;
        float4* o4 = (float4*)nsum;
        for (; i < n4; i += st) {
            float4 x = a4[i], y = b4[i];
            o4[i] = make_float4(x.x + y.x, x.y + y.y, x.z + y.z, x.w + y.w);
        }
    }
}

__global__ void build_qin_conv(const float* __restrict__ conv,
                               __nv_bfloat16* __restrict__ qhi, __nv_bfloat16* __restrict__ qlo)
{
    int m = blockIdx.x;
    for (int j = threadIdx.x; j < QPAD; j += blockDim.x) {
        float v = (j < DN) ? conv[(size_t)m * DN + j] : 0.f;
        __nv_bfloat16 h, l; split_bf16(v, h, l);
        qhi[(size_t)m * QPAD + j] = h;
        qlo[(size_t)m * QPAD + j] = l;
    }
}

// ---------------- fused kv-build + attention + weighted-sum (two-head fused) -------
__global__ void __launch_bounds__(256) attn_fused(
    const float* __restrict__ qk,
    const float* __restrict__ feat,          // null -> gather nsum
    const int* __restrict__ idsA, const int* __restrict__ eidsA,
    const float* __restrict__ tA, const float* __restrict__ ntA, int nA,
    const int* __restrict__ idsB, const int* __restrict__ eidsB,
    const float* __restrict__ tB, const float* __restrict__ ntB,
    const float* __restrict__ nsum, const float* __restrict__ edge_raw,
    const float* __restrict__ time_w, const float* __restrict__ time_b,
    __nv_bfloat16* __restrict__ wshi, __nv_bfloat16* __restrict__ wslo)
{
    const float SCALE = 0.08574929257125442f;   // 136^-0.5
    __shared__ __align__(16) float kvs[Kn][KVPAD];
    __shared__ __align__(16) float qks[WSP];
    __shared__ float att[2 * Kn];
    __shared__ int   sids[Kn];

    int m = blockIdx.x;
    int tid = threadIdx.x, wid = tid >> 5, lane = tid & 31;
    const uint32_t kvs_b = smem_u32(kvs);

    const int* nbr_ids; const int* nbr_eids; const float* nbr_t; float tm;
    if (m < nA) {
        nbr_ids = idsA + (size_t)m * Kn;
        nbr_eids = eidsA + (size_t)m * Kn;
        nbr_t = ntA + (size_t)m * Kn;
        tm = tA[m];
    } else {
        int mm = m - nA;
        nbr_ids = idsB + (size_t)mm * Kn;
        nbr_eids = eidsB + (size_t)mm * Kn;
        nbr_t = ntB + (size_t)mm * Kn;
        tm = tB[mm];
    }

    if (tid < Kn) sids[tid] = nbr_ids[tid];
    if (tid < 224)
        cpa16(smem_u32(qks) + tid * 16, (const float4*)(qk + (size_t)m * WSP) + tid);

    for (int p = wid; p < Kn; p += 8) {
        int nid = nbr_ids[p];
        int eid = nbr_eids[p];
        const float4* nsrc = feat ? (const float4*)(feat + ((size_t)m * Kn + p) * DN)
                                  : (const float4*)(nsum + (size_t)nid * DN);
        const float4* esrc = (const float4*)(edge_raw + (size_t)eid * DE);
        uint32_t dst = kvs_b + (uint32_t)p * (KVPAD * 4);
#pragma unroll
        for (int it = 0; it < 3; it++) {
            int ch = lane + it * 32;
            if (ch < 86) {
                if (ch < 43) cpa16(dst + ch * 16, nsrc + ch);
                else         cpa16(dst + 688 + (ch - 43) * 16, esrc + (ch - 43));
            }
        }
        float dt = __fadd_rn(tm, -nbr_t[p]);
#pragma unroll
        for (int it = 0; it < 4; it++) {
            int j = lane + it * 32;
            if (j < 100)
                kvs[p][344 + j] = cosf(__fadd_rn(__fmul_rn(dt, time_w[j]), time_b[j]));
        }
        if (lane < 4) kvs[p][444 + lane] = 0.f;
    }
    CP_COMMIT();
    CP_WAIT0();
    __syncthreads();

    for (int kk = wid; kk < Kn; kk += 8) {
        float s0 = 0.f, s1 = 0.f;
        for (int d = lane; d < KDd; d += 32) {
            float v = kvs[kk][d];
            s0 += qks[d] * v;
            s1 += qks[448 + d] * v;
        }
#pragma unroll
        for (int o = 16; o; o >>= 1) {
            s0 += __shfl_xor_sync(0xffffffffu, s0, o);
            s1 += __shfl_xor_sync(0xffffffffu, s1, o);
        }
        if (lane == 0) {
            bool msk = (sids[kk] == 0);
            att[kk]      = msk ? -1e10f : s0 * SCALE;
            att[Kn + kk] = msk ? -1e10f : s1 * SCALE;
        }
    }
    __syncthreads();

    if (tid < 2) {
        int h = tid;
        float mx = -INFINITY;
        for (int kk = 0; kk < Kn; kk++) mx = fmaxf(mx, att[h * Kn + kk]);
        float sum = 0.f;
        for (int kk = 0; kk < Kn; kk++) { float e = expf(att[h*Kn+kk] - mx); att[h*Kn+kk] = e; sum += e; }
        float inv = 1.f / sum;
        for (int kk = 0; kk < Kn; kk++) att[h * Kn + kk] *= inv;
    }
    __syncthreads();

    for (int jj = tid; jj < 448; jj += 256) {
        float a0 = 0.f, a1 = 0.f;
#pragma unroll
        for (int kk = 0; kk < Kn; kk++) {
            float v = kvs[kk][jj];
            a0 += att[kk] * v;
            a1 += att[Kn + kk] * v;
        }
        __nv_bfloat16 h0, l0, h1, l1;
        split_bf16(a0, h0, l0);
        split_bf16(a1, h1, l1);
        wshi[(size_t)m * WSP + jj] = h0;
        wslo[(size_t)m * WSP + jj] = l0;
        wshi[(size_t)m * WSP + 448 + jj] = h1;
        wslo[(size_t)m * WSP + 448 + jj] = l1;
    }
}

// ---------------- residual + bias + LayerNorm + cat ----------------
__global__ void lncat_kernel(const float* __restrict__ o, const float* __restrict__ bo,
                             const __nv_bfloat16* __restrict__ resHi, const __nv_bfloat16* __restrict__ resLo,
                             const __nv_bfloat16* __restrict__ nfHi, const __nv_bfloat16* __restrict__ nfLo,
                             const float* __restrict__ time_b,
                             const float* __restrict__ gam, const float* __restrict__ bet,
                             __nv_bfloat16* __restrict__ chi, __nv_bfloat16* __restrict__ clo)
{
    int m = blockIdx.x;
    int tid = threadIdx.x;
    __shared__ float buf[QD];
    __shared__ float red[32];
    for (int j = tid; j < QD; j += 256) {
        float res = (j < DN)
            ? join_bf16(resHi[(size_t)m * QPAD + j], resLo[(size_t)m * QPAD + j])
            : cosf(time_b[j - DN]);
        buf[j] = o[(size_t)m * QD + j] + bo[j] + res;
    }
    __syncthreads();
    float s = 0.f;
    for (int j = tid; j < QD; j += 256) s += buf[j];
#pragma unroll
    for (int off = 16; off; off >>= 1) s += __shfl_xor_sync(0xffffffffu, s, off);
    if ((tid & 31) == 0) red[tid >> 5] = s;
    __syncthreads();
    if (tid < 32) {
        float t = (tid < 8) ? red[tid] : 0.f;
#pragma unroll
        for (int off = 4; off; off >>= 1) t += __shfl_xor_sync(0xffffffffu, t, off);
        if (tid == 0) red[0] = t;
    }
    __syncthreads();
    float mu = red[0] / (float)QD;
    __syncthreads();
    float s2 = 0.f;
    for (int j = tid; j < QD; j += 256) { float d = buf[j] - mu; s2 += d * d; }
#pragma unroll
    for (int off = 16; off; off >>= 1) s2 += __shfl_xor_sync(0xffffffffu, s2, off);
    if ((tid & 31) == 0) red[tid >> 5] = s2;
    __syncthreads();
    if (tid < 32) {
        float t = (tid < 8) ? red[tid] : 0.f;
#pragma unroll
        for (int off = 4; off; off >>= 1) t += __shfl_xor_sync(0xffffffffu, t, off);
        if (tid == 0) red[0] = t;
    }
    __syncthreads();
    float var = red[0] / (float)QD;
    float rinv = 1.0f / sqrtf(var + 1e-5f);
    for (int j = tid; j < KVPAD; j += 256) {
        float vv;
        if (j < QD)
            vv = (buf[j] - mu) * rinv * gam[j] + bet[j];
        else if (j < KDd)
            vv = join_bf16(nfHi[(size_t)m * QPAD + (j - QD)], nfLo[(size_t)m * QPAD + (j - QD)]);
        else
            vv = 0.f;
        __nv_bfloat16 hi, lo; split_bf16(vv, hi, lo);
        chi[(size_t)m * KVPAD + j] = hi;
        clo[(size_t)m * KVPAD + j] = lo;
    }
}

// ---------------- host ----------------
extern "C" void kernel_launch(void* const* d_in, const int* in_sizes, int n_in,
                              void* d_out, int out_size)
{
    (void)in_sizes; (void)n_in; (void)out_size;
    const float* node_raw = (const float*)d_in[0];
    const float* edge_raw = (const float*)d_in[1];
    const float* memories = (const float*)d_in[2];
    const float* t_node   = (const float*)d_in[3];
    const float* t_n1     = (const float*)d_in[4];
    const float* t_n2     = (const float*)d_in[5];
    const float* time_w   = (const float*)d_in[6];
    const float* time_b   = (const float*)d_in[7];
    const float* Wq       = (const float*)d_in[8];
    const float* Wk       = (const float*)d_in[9];
    const float* Wv       = (const float*)d_in[10];
    const float* Wo       = (const float*)d_in[11];
    const float* bo       = (const float*)d_in[12];
    const float* ln_g     = (const float*)d_in[13];
    const float* ln_b     = (const float*)d_in[14];
    const float* m_w1     = (const float*)d_in[15];
    const float* m_b1     = (const float*)d_in[16];
    const float* m_w2     = (const float*)d_in[17];
    const float* m_b2     = (const float*)d_in[18];
    const int* node_ids   = (const int*)d_in[19];
    const int* n1_ids     = (const int*)d_in[20];
    const int* n1_eids    = (const int*)d_in[21];
    const int* n2_ids     = (const int*)d_in[22];
    const int* n2_eids    = (const int*)d_in[23];
    float* out = (float*)d_out;

    float *nsum, *qkbuf, *obuf, *conv, *qkbias;
    __nv_bfloat16 *qin_hi, *qin_lo, *ws_hi, *ws_lo, *cat_hi, *cat_lo, *h_hi, *h_lo;
    __nv_bfloat16 *wqkt, *wvot, *w1t, *w2t;
    cudaGetSymbolAddress((void**)&nsum, g_nsum);
    cudaGetSymbolAddress((void**)&qkbuf, g_qk);
    cudaGetSymbolAddress((void**)&obuf, g_o);
    cudaGetSymbolAddress((void**)&conv, g_conv);
    cudaGetSymbolAddress((void**)&qkbias, g_qkbias);
    cudaGetSymbolAddress((void**)&qin_hi, g_qin_hi);
    cudaGetSymbolAddress((void**)&qin_lo, g_qin_lo);
    cudaGetSymbolAddress((void**)&ws_hi, g_ws_hi);
    cudaGetSymbolAddress((void**)&ws_lo, g_ws_lo);
    cudaGetSymbolAddress((void**)&cat_hi, g_cat_hi);
    cudaGetSymbolAddress((void**)&cat_lo, g_cat_lo);
    cudaGetSymbolAddress((void**)&h_hi, g_h_hi);
    cudaGetSymbolAddress((void**)&h_lo, g_h_lo);
    cudaGetSymbolAddress((void**)&wqkt, g_wqkt);
    cudaGetSymbolAddress((void**)&wvot, g_wvot);
    cudaGetSymbolAddress((void**)&w1t, g_w1t);
    cudaGetSymbolAddress((void**)&w2t, g_w2t);

    cudaFuncSetAttribute(mma_gemm_kernel, cudaFuncAttributeMaxDynamicSharedMemorySize, NSTAGE * STAGE_B);
    cudaFuncSetAttribute(wfold_build, cudaFuncAttributeMaxDynamicSharedMemorySize, 2 * 64 * 137 * 4);

    auto wpq = [&](int l, int hl) { return wqkt + ((size_t)(l * 2 + hl)) * (QKN * WKP); };
    auto wpv = [&](int l, int hl) { return wvot + ((size_t)(l * 2 + hl)) * (288 * WSP); };
    auto wp1 = [&](int l, int hl) { return w1t + ((size_t)(l * 2 + hl)) * (HPAD * KVPAD); };
    auto wp2 = [&](int l, int hl) { return w2t + ((size_t)(l * 2 + hl)) * (HPAD * HPAD); };

    auto rungemm = [&](const __nv_bfloat16* aH, const __nv_bfloat16* aL,
                       const __nv_bfloat16* wH, const __nv_bfloat16* wL,
                       const float* bias, int relu, float* oF,
                       __nv_bfloat16* oH, __nv_bfloat16* oL,
                       int M, int KpadA, int KpadW, int Klog, int Nlog, int padKout) {
        dim3 grid((Nlog + 95) / 96, M / 128);
        mma_gemm_kernel<<<grid, 256, NSTAGE * STAGE_B>>>(aH, aL, wH, wL, bias, relu,
                                                         oF, oH, oL, KpadA, KpadW, Klog, Nlog, padKout);
    };

    // 1: wfold  2: qkbias  3: build_nf+presum  4: qk GEMM (profiled sentinel)
    wfold_build<<<dim3(WSP/64, QKN/64, 4), 256, 2*64*137*4>>>(
        Wq, Wk, Wv, Wo, wpq(0,0), wpq(0,1), wpv(0,0), wpv(0,1));
    qkbias_build<<<dim3(WSP, 2), 128>>>(wpq(0,0), wpq(0,1), time_b, qkbias,
                                        (size_t)2 * QKN * WKP);
    build_nf_qin<<<MT + PBLK, 256>>>(n1_ids, node_ids, M2, memories, node_raw,
                                     qin_hi, qin_lo, nsum, (size_t)NNODE * DN / 4, MT);
    rungemm(qin_hi, qin_lo, wpq(0,0), wpq(0,1), qkbias, 0,
            qkbuf, nullptr, nullptr, MT, QPAD, WKP, DN, WSP, 0);
    WJobs jobs;
    for (int l = 0; l < 2; l++) {
        jobs.j[l*2+0] = { m_w1 + (size_t)l*KDd*DN, wp1(l,0), wp1(l,1), KDd, DN, KVPAD };
        jobs.j[l*2+1] = { m_w2 + (size_t)l*DN*DN,  wp2(l,0), wp2(l,1), DN,  DN, HPAD  };
    }
    wconv_all<<<dim3(KVPAD/32, HPAD/32, 4), dim3(32, 32)>>>(jobs);

    // ---- phase A+B tail ----
    attn_fused<<<MT, 256>>>(qkbuf, nullptr, n2_ids, n2_eids, t_n1, t_n2, M2,
                            n1_ids, n1_eids, t_node, t_n1,
                            nsum, edge_raw, time_w, time_b, ws_hi, ws_lo);
    rungemm(ws_hi, ws_lo, wpv(0,0), wpv(0,1), nullptr, 0,
            obuf, nullptr, nullptr, MT, WSP, WSP, WSP, QD, 0);
    lncat_kernel<<<MT, 256>>>(obuf, bo, qin_hi, qin_lo, qin_hi, qin_lo, time_b,
                              ln_g, ln_b, cat_hi, cat_lo);
    rungemm(cat_hi, cat_lo, wp1(0,0), wp1(0,1), m_b1, 1,
            nullptr, h_hi, h_lo, MT, KVPAD, KVPAD, KVPAD, DN, HPAD);
    rungemm(h_hi, h_lo, wp2(0,0), wp2(0,1), m_b2, 0,
            conv, nullptr, nullptr, MT, HPAD, HPAD, DN, DN, 0);

    // ---- phase C: layer 1 over center nodes ----
    build_qin_conv<<<Bsz, 256>>>(conv + (size_t)M2 * DN, qin_hi, qin_lo);
    rungemm(qin_hi, qin_lo, wpq(1,0), wpq(1,1), qkbias + WSP, 0,
            qkbuf, nullptr, nullptr, Bsz, QPAD, WKP, DN, WSP, 0);
    attn_fused<<<Bsz, 256>>>(qkbuf, conv, n1_ids, n1_eids, t_node, t_n1, Bsz,
                             n1_ids, n1_eids, t_node, t_n1,
                             nsum, edge_raw, time_w, time_b, ws_hi, ws_lo);
    rungemm(ws_hi, ws_lo, wpv(1,0), wpv(1,1), nullptr, 0,
            obuf, nullptr, nullptr, Bsz, WSP, WSP, WSP, QD, 0);
    lncat_kernel<<<Bsz, 256>>>(obuf, bo + QD, qin_hi, qin_lo,
                               qin_hi + (size_t)M2 * QPAD, qin_lo + (size_t)M2 * QPAD,
                               time_b, ln_g + QD, ln_b + QD, cat_hi, cat_lo);
    rungemm(cat_hi, cat_lo, wp1(1,0), wp1(1,1), m_b1 + DN, 1,
            nullptr, h_hi, h_lo, Bsz, KVPAD, KVPAD, KVPAD, DN, HPAD);
    rungemm(h_hi, h_lo, wp2(1,0), wp2(1,1), m_b2 + DN, 0,
            out, nullptr, nullptr, Bsz, HPAD, HPAD, DN, DN, 0);
}